// round 5
// baseline (speedup 1.0000x reference)
#include <cuda_runtime.h>
#include <cuda_bf16.h>
#include <cstdint>
#include <math.h>

#define NPTS 8192
#define SSZ  1024
#define EPSF 1e-7f

__device__ __align__(16) float g_misc[2784];
__device__ __align__(16) uint4 g_bf1[4096];   // f1 B-fragments
__device__ __align__(16) uint4 g_bf2[8192];   // f2 B-fragments

#define MSF_W1T 0
#define MSF_B1  256
#define MSF_W2T 288
#define MSF_B2  2336
#define MSF_FB1 2400
#define MSF_FB2 2528

// smem byte offsets
#define SM_MISC 0
#define SM_PART 11136
#define SM_AH   19456
#define SM_AL   54272
#define SM_TOTAL 89088
#define AST 68          // A-image row stride in words (conflict-free for ldmatrix)

__device__ __forceinline__ uint32_t pack_hi(float a, float b) {
    __nv_bfloat162 h;
    h.x = __float2bfloat16_rn(a);
    h.y = __float2bfloat16_rn(b);
    return *(uint32_t*)&h;
}
__device__ __forceinline__ uint32_t pack_lo(float a, float b) {
    float ra = a - __bfloat162float(__float2bfloat16_rn(a));
    float rb = b - __bfloat162float(__float2bfloat16_rn(b));
    return pack_hi(ra, rb);
}
__device__ __forceinline__ uint32_t smem_u32(const void* p) {
    uint32_t a;
    asm("{ .reg .u64 t; cvta.to.shared.u64 t, %1; cvt.u32.u64 %0, t; }" : "=r"(a) : "l"(p));
    return a;
}
__device__ __forceinline__ void lda4(uint32_t r[4], uint32_t sbase, int rowbase, int s, int lane) {
    int row = rowbase + (lane & 7) + ((lane >> 3) & 1) * 8;
    int kw  = 8 * s + ((lane >> 4) << 2);
    uint32_t addr = sbase + (uint32_t)(row * (AST * 4) + kw * 4);
    asm volatile("ldmatrix.sync.aligned.m8n8.x4.shared.b16 {%0,%1,%2,%3}, [%4];"
        : "=r"(r[0]), "=r"(r[1]), "=r"(r[2]), "=r"(r[3]) : "r"(addr));
}
__device__ __forceinline__ void mma_bf16(float* d, const uint32_t* a, uint32_t b0, uint32_t b1) {
    asm volatile("mma.sync.aligned.m16n8k16.row.col.f32.bf16.bf16.f32 "
        "{%0,%1,%2,%3}, {%4,%5,%6,%7}, {%8,%9}, {%0,%1,%2,%3};"
        : "+f"(d[0]), "+f"(d[1]), "+f"(d[2]), "+f"(d[3])
        : "r"(a[0]), "r"(a[1]), "r"(a[2]), "r"(a[3]), "r"(b0), "r"(b1));
}
__device__ __forceinline__ float clamp1(float x) {
    return fminf(fmaxf(x, -1.0f + EPSF), 1.0f - EPSF);
}

// ---------------- prep: fold BN, pack fragments ----------------
__global__ void prep_kernel(
    const float* __restrict__ ew1, const float* __restrict__ eb1, const float* __restrict__ eg1,
    const float* __restrict__ ebeta1, const float* __restrict__ em1, const float* __restrict__ ev1,
    const float* __restrict__ ew2, const float* __restrict__ eb2, const float* __restrict__ eg2,
    const float* __restrict__ ebeta2, const float* __restrict__ em2, const float* __restrict__ ev2,
    const float* __restrict__ fw1, const float* __restrict__ fb1, const float* __restrict__ fg1,
    const float* __restrict__ fbeta1, const float* __restrict__ fm1, const float* __restrict__ fv1,
    const float* __restrict__ fw2, const float* __restrict__ fb2, const float* __restrict__ fg2,
    const float* __restrict__ fbeta2, const float* __restrict__ fm2, const float* __restrict__ fv2)
{
    int t = blockIdx.x * blockDim.x + threadIdx.x;
    int stride = gridDim.x * blockDim.x;

    for (int i = t; i < 4096; i += stride) {
        int lane = i & 31, s = (i >> 5) & 7, nt = i >> 8;
        int n = nt * 8 + (lane >> 2);
        int k0 = s * 16 + (lane & 3) * 2;
        float sc = fg1[n] * rsqrtf(fv1[n] + 1e-5f);
        float v00 = fw1[n * 128 + k0] * sc,     v01 = fw1[n * 128 + k0 + 1] * sc;
        float v10 = fw1[n * 128 + k0 + 8] * sc, v11 = fw1[n * 128 + k0 + 9] * sc;
        uint4 r;
        r.x = pack_hi(v00, v01); r.y = pack_hi(v10, v11);
        r.z = pack_lo(v00, v01); r.w = pack_lo(v10, v11);
        g_bf1[i] = r;
    }
    for (int i = t; i < 8192; i += stride) {
        int lane = i & 31, s = (i >> 5) & 7, nt = i >> 8;
        int n = nt * 8 + (lane >> 2);
        int k0 = s * 16 + (lane & 3) * 2;
        float sc = fg2[n] * rsqrtf(fv2[n] + 1e-5f);
        float v00 = fw2[n * 128 + k0] * sc,     v01 = fw2[n * 128 + k0 + 1] * sc;
        float v10 = fw2[n * 128 + k0 + 8] * sc, v11 = fw2[n * 128 + k0 + 9] * sc;
        uint4 r;
        r.x = pack_hi(v00, v01); r.y = pack_hi(v10, v11);
        r.z = pack_lo(v00, v01); r.w = pack_lo(v10, v11);
        g_bf2[i] = r;
    }
    for (int i = t; i < 256; i += stride) {
        int o = i & 31, c = i >> 5;
        g_misc[MSF_W1T + c * 32 + o] = ew1[o * 8 + c] * (eg1[o] * rsqrtf(ev1[o] + 1e-5f));
    }
    for (int i = t; i < 32; i += stride) {
        float sc = eg1[i] * rsqrtf(ev1[i] + 1e-5f);
        g_misc[MSF_B1 + i] = (eb1[i] - em1[i]) * sc + ebeta1[i];
    }
    for (int i = t; i < 2048; i += stride) {
        int o = i & 63, c = i >> 6;
        g_misc[MSF_W2T + c * 64 + o] = ew2[o * 32 + c] * (eg2[o] * rsqrtf(ev2[o] + 1e-5f));
    }
    for (int i = t; i < 64; i += stride) {
        float sc = eg2[i] * rsqrtf(ev2[i] + 1e-5f);
        g_misc[MSF_B2 + i] = (eb2[i] - em2[i]) * sc + ebeta2[i];
    }
    for (int i = t; i < 128; i += stride) {
        float sc = fg1[i] * rsqrtf(fv1[i] + 1e-5f);
        g_misc[MSF_FB1 + i] = (fb1[i] - fm1[i]) * sc + fbeta1[i];
    }
    for (int i = t; i < 256; i += stride) {
        float sc = fg2[i] * rsqrtf(fv2[i] + 1e-5f);
        g_misc[MSF_FB2 + i] = (fb2[i] - fm2[i]) * sc + fbeta2[i];
    }
}

// ---------------- main kernel: 512 threads, 16 warps ----------------
__global__ __launch_bounds__(512, 1) void main_kernel(
    const float* __restrict__ contour,
    const float* __restrict__ loa,
    const float* __restrict__ prev,
    float* __restrict__ out)
{
    extern __shared__ char smem[];
    const uint32_t sb = smem_u32(smem);
    float* ms = (float*)(smem + SM_MISC);
    float* part = (float*)(smem + SM_PART);
    uint32_t* ah = (uint32_t*)(smem + SM_AH);
    uint32_t* al = (uint32_t*)(smem + SM_AL);

    const int t = threadIdx.x;
    const int lane = t & 31;
    const int warp = t >> 5;
    const int b = blockIdx.x >> 8;
    const int s_base = (blockIdx.x & 255) * 4;

    // stage misc weights to smem
    {
        const uint4* src = (const uint4*)g_misc;
        uint4* dst = (uint4*)ms;
        for (int i = t; i < 696; i += 512) dst[i] = src[i];
    }

    // ---- geometry (per row; replicated across the 4 channel-quarters) ----
    const int row = t & 127;
    const int oq = t >> 7;          // 0..3
    const int k = row & 31;
    const int s = s_base + (row >> 5);
    int nii;
    if (s == SSZ - 1) nii = NPTS - 1;
    else nii = (int)((double)s * ((double)(NPTS - 1) / (double)(SSZ - 1)));
    const int g  = (nii - 16 + k) & (NPTS - 1);
    const int gp = (nii - 16 + k - 1) & (NPTS - 1);

    float rif[8];
    {
        const float2* cptr = (const float2*)(contour + (size_t)b * NPTS * 2);
        const float2* lptr = (const float2*)(loa + (size_t)b * NPTS * 2);
        float2 xi = cptr[g], lxi = lptr[g];
        float2 xp = cptr[gp], lxp = lptr[gp];
        float2 ci = cptr[nii], lci = lptr[nii];

        float vx = xi.x - ci.x, vy = xi.y - ci.y;
        float f4 = sqrtf(vx * vx + vy * vy);
        float inv = 1.0f / (f4 + EPSF);
        float ux = vx * inv, uy = vy * inv;
        float a1 = lci.x * ux + lci.y * uy;
        float a2 = -(lxi.x * ux + lxi.y * uy);
        float f3 = ((a1 < a2) ? 1.0f : -1.0f) * acosf(clamp1(lxi.x * lci.x + lxi.y * lci.y));

        float vpx, vpy, lmx, lmy, rux, ruy;
        if (k > 0) {
            vpx = xi.x - xp.x; vpy = xi.y - xp.y;
            lmx = lxp.x;       lmy = lxp.y;
            float pvx = xp.x - ci.x, pvy = xp.y - ci.y;
            float invp = 1.0f / (sqrtf(pvx * pvx + pvy * pvy) + EPSF);
            rux = pvx * invp; ruy = pvy * invp;
        } else {
            vpx = vpy = lmx = lmy = rux = ruy = 0.0f;
        }
        float f8 = sqrtf(vpx * vpx + vpy * vpy);
        float inv8 = 1.0f / (f8 + EPSF);
        float upx = vpx * inv8, upy = vpy * inv8;
        float a4 = upx * lxi.x + upy * lxi.y;
        float a5 = upx * lmx + upy * lmy;
        float f7 = ((a4 < a5) ? 1.0f : -1.0f) * acosf(clamp1(lxi.x * lmx + lxi.y * lmy));
        float d2 = acosf(clamp1(ux * rux + uy * ruy));

        rif[0] = f4; rif[1] = d2; rif[2] = a1; rif[3] = a2;
        rif[4] = f3; rif[5] = a4; rif[6] = a5; rif[7] = f7;
    }
    __syncthreads();  // misc staged

    // ---- e1: 8 -> 32 (full, per thread) ----
    float h1v[32];
    #pragma unroll
    for (int o4 = 0; o4 < 8; o4++) {
        float4 bb = *(const float4*)&ms[MSF_B1 + o4 * 4];
        h1v[o4 * 4 + 0] = bb.x; h1v[o4 * 4 + 1] = bb.y;
        h1v[o4 * 4 + 2] = bb.z; h1v[o4 * 4 + 3] = bb.w;
    }
    #pragma unroll
    for (int c = 0; c < 8; c++) {
        float rc = rif[c];
        #pragma unroll
        for (int o4 = 0; o4 < 8; o4++) {
            float4 w = *(const float4*)&ms[MSF_W1T + c * 32 + o4 * 4];
            h1v[o4 * 4 + 0] += w.x * rc; h1v[o4 * 4 + 1] += w.y * rc;
            h1v[o4 * 4 + 2] += w.z * rc; h1v[o4 * 4 + 3] += w.w * rc;
        }
    }
    #pragma unroll
    for (int o = 0; o < 32; o++) h1v[o] = fmaxf(h1v[o], 0.0f);

    // ---- e2: 32 -> 64; this quarter's 16 channels ----
    float acc2[16];
    {
        const int o0 = 16 * oq;
        #pragma unroll
        for (int j4 = 0; j4 < 4; j4++) {
            float4 bb = *(const float4*)&ms[MSF_B2 + o0 + j4 * 4];
            acc2[j4 * 4 + 0] = bb.x; acc2[j4 * 4 + 1] = bb.y;
            acc2[j4 * 4 + 2] = bb.z; acc2[j4 * 4 + 3] = bb.w;
        }
        #pragma unroll 4
        for (int c = 0; c < 32; c++) {
            float hc = h1v[c];
            #pragma unroll
            for (int j4 = 0; j4 < 4; j4++) {
                float4 w = *(const float4*)&ms[MSF_W2T + c * 64 + o0 + j4 * 4];
                acc2[j4 * 4 + 0] += w.x * hc; acc2[j4 * 4 + 1] += w.y * hc;
                acc2[j4 * 4 + 2] += w.z * hc; acc2[j4 * 4 + 3] += w.w * hc;
            }
        }
    }
    // e2 channels -> A words [row][8*oq + jp]
    #pragma unroll
    for (int jp = 0; jp < 8; jp++) {
        float v0 = fmaxf(acc2[2 * jp], 0.0f);
        float v1 = fmaxf(acc2[2 * jp + 1], 0.0f);
        int wi = row * AST + 8 * oq + jp;
        ah[wi] = pack_hi(v0, v1);
        al[wi] = pack_lo(v0, v1);
    }
    // prev gather: channels [16*oq .. +16) -> A words [row][32 + 8*oq + jp]
    {
        const float* pb = prev + ((size_t)b * 64 + 16 * (size_t)oq) * NPTS + g;
        #pragma unroll
        for (int jp = 0; jp < 8; jp++) {
            float v0 = pb[(size_t)(2 * jp) * NPTS];
            float v1 = pb[(size_t)(2 * jp + 1) * NPTS];
            int wi = row * AST + 32 + 8 * oq + jp;
            ah[wi] = pack_hi(v0, v1);
            al[wi] = pack_lo(v0, v1);
        }
    }
    __syncthreads();

    const int mg = warp >> 2;       // 0..3 : rows 32*mg
    const int ng = warp & 3;        // 0..3
    const int jj = lane & 3;
    const int qq = lane >> 2;
    const uint32_t sbAH = sb + SM_AH, sbAL = sb + SM_AL;

    // ================= f1: 128 -> 128 =================
    float f1acc[2][4][4];
    {
        #pragma unroll
        for (int nt = 0; nt < 4; nt++) {
            int cb = (ng * 4 + nt) * 8 + 2 * jj;
            float be = ms[MSF_FB1 + cb], bo = ms[MSF_FB1 + cb + 1];
            #pragma unroll
            for (int mt = 0; mt < 2; mt++) {
                f1acc[mt][nt][0] = be; f1acc[mt][nt][1] = bo;
                f1acc[mt][nt][2] = be; f1acc[mt][nt][3] = bo;
            }
        }
        uint4 bcur[4];
        #pragma unroll
        for (int nt = 0; nt < 4; nt++)
            bcur[nt] = __ldg(&g_bf1[(ng * 4 + nt) * 256 + lane]);
        #pragma unroll
        for (int sstep = 0; sstep < 8; sstep++) {
            uint4 bnxt[4];
            if (sstep < 7) {
                #pragma unroll
                for (int nt = 0; nt < 4; nt++)
                    bnxt[nt] = __ldg(&g_bf1[(ng * 4 + nt) * 256 + (sstep + 1) * 32 + lane]);
            }
            #pragma unroll
            for (int mt = 0; mt < 2; mt++) {
                uint32_t a4[4];
                lda4(a4, sbAH, mg * 32 + 16 * mt, sstep, lane);
                #pragma unroll
                for (int nt = 0; nt < 4; nt++) {
                    mma_bf16(f1acc[mt][nt], a4, bcur[nt].x, bcur[nt].y);
                    mma_bf16(f1acc[mt][nt], a4, bcur[nt].z, bcur[nt].w);
                }
                lda4(a4, sbAL, mg * 32 + 16 * mt, sstep, lane);
                #pragma unroll
                for (int nt = 0; nt < 4; nt++)
                    mma_bf16(f1acc[mt][nt], a4, bcur[nt].x, bcur[nt].y);
            }
            if (sstep < 7) {
                #pragma unroll
                for (int nt = 0; nt < 4; nt++) bcur[nt] = bnxt[nt];
            }
        }
    }
    __syncthreads();   // all f1 reads of A done; safe to overwrite

    // relu + split + store f1 outputs back into A image
    #pragma unroll
    for (int mt = 0; mt < 2; mt++) {
        #pragma unroll
        for (int nt = 0; nt < 4; nt++) {
            int r0 = mg * 32 + 16 * mt + qq;
            int wi = (ng * 4 + nt) * 4 + jj;
            float v0 = fmaxf(f1acc[mt][nt][0], 0.0f), v1 = fmaxf(f1acc[mt][nt][1], 0.0f);
            ah[r0 * AST + wi] = pack_hi(v0, v1);
            al[r0 * AST + wi] = pack_lo(v0, v1);
            float v2 = fmaxf(f1acc[mt][nt][2], 0.0f), v3 = fmaxf(f1acc[mt][nt][3], 0.0f);
            ah[(r0 + 8) * AST + wi] = pack_hi(v2, v3);
            al[(r0 + 8) * AST + wi] = pack_lo(v2, v3);
        }
    }
    __syncthreads();

    // ================= f2: 128 -> 256 (+ k-max) =================
    #pragma unroll 1
    for (int cnk = 0; cnk < 2; cnk++) {
        const int ntg0 = ng * 8 + cnk * 4;
        float acc[2][4][4];
        #pragma unroll
        for (int nt = 0; nt < 4; nt++) {
            int cb = (ntg0 + nt) * 8 + 2 * jj;
            float be = ms[MSF_FB2 + cb], bo = ms[MSF_FB2 + cb + 1];
            #pragma unroll
            for (int mt = 0; mt < 2; mt++) {
                acc[mt][nt][0] = be; acc[mt][nt][1] = bo;
                acc[mt][nt][2] = be; acc[mt][nt][3] = bo;
            }
        }
        uint4 bcur[4];
        #pragma unroll
        for (int nt = 0; nt < 4; nt++)
            bcur[nt] = __ldg(&g_bf2[(ntg0 + nt) * 256 + lane]);
        #pragma unroll
        for (int sstep = 0; sstep < 8; sstep++) {
            uint4 bnxt[4];
            if (sstep < 7) {
                #pragma unroll
                for (int nt = 0; nt < 4; nt++)
                    bnxt[nt] = __ldg(&g_bf2[(ntg0 + nt) * 256 + (sstep + 1) * 32 + lane]);
            }
            #pragma unroll
            for (int mt = 0; mt < 2; mt++) {
                uint32_t a4[4];
                lda4(a4, sbAH, mg * 32 + 16 * mt, sstep, lane);
                #pragma unroll
                for (int nt = 0; nt < 4; nt++) {
                    mma_bf16(acc[mt][nt], a4, bcur[nt].x, bcur[nt].y);
                    mma_bf16(acc[mt][nt], a4, bcur[nt].z, bcur[nt].w);
                }
                lda4(a4, sbAL, mg * 32 + 16 * mt, sstep, lane);
                #pragma unroll
                for (int nt = 0; nt < 4; nt++)
                    mma_bf16(acc[mt][nt], a4, bcur[nt].x, bcur[nt].y);
            }
            if (sstep < 7) {
                #pragma unroll
                for (int nt = 0; nt < 4; nt++) bcur[nt] = bnxt[nt];
            }
        }
        // relu + max over this warp's 16-row k-half, stage to part
        #pragma unroll
        for (int mt = 0; mt < 2; mt++) {
            #pragma unroll
            for (int nt = 0; nt < 4; nt++) {
                float me = fmaxf(fmaxf(acc[mt][nt][0], acc[mt][nt][2]), 0.0f);
                float mo = fmaxf(fmaxf(acc[mt][nt][1], acc[mt][nt][3]), 0.0f);
                me = fmaxf(me, __shfl_xor_sync(0xffffffffu, me, 4));
                me = fmaxf(me, __shfl_xor_sync(0xffffffffu, me, 8));
                me = fmaxf(me, __shfl_xor_sync(0xffffffffu, me, 16));
                mo = fmaxf(mo, __shfl_xor_sync(0xffffffffu, mo, 4));
                mo = fmaxf(mo, __shfl_xor_sync(0xffffffffu, mo, 8));
                mo = fmaxf(mo, __shfl_xor_sync(0xffffffffu, mo, 16));
                if (lane < 4) {
                    int col = (ntg0 + nt) * 8 + 2 * lane;
                    part[mg * 512 + mt * 256 + col] = me;
                    part[mg * 512 + mt * 256 + col + 1] = mo;
                }
            }
        }
    }
    __syncthreads();

    // ---- final: combine k-halves, coalesced store (first 256 threads) ----
    if (t < 256) {
        float4 v;
        v.x = fmaxf(part[0 * 512 + t], part[0 * 512 + 256 + t]);
        v.y = fmaxf(part[1 * 512 + t], part[1 * 512 + 256 + t]);
        v.z = fmaxf(part[2 * 512 + t], part[2 * 512 + 256 + t]);
        v.w = fmaxf(part[3 * 512 + t], part[3 * 512 + 256 + t]);
        *(float4*)(out + ((size_t)(b * 256 + t)) * SSZ + s_base) = v;
    }
}

extern "C" void kernel_launch(void* const* d_in, const int* in_sizes, int n_in,
                              void* d_out, int out_size)
{
    cudaFuncSetAttribute(main_kernel, cudaFuncAttributeMaxDynamicSharedMemorySize, SM_TOTAL);

    prep_kernel<<<64, 256>>>(
        (const float*)d_in[3],  (const float*)d_in[4],  (const float*)d_in[5],
        (const float*)d_in[6],  (const float*)d_in[7],  (const float*)d_in[8],
        (const float*)d_in[9],  (const float*)d_in[10], (const float*)d_in[11],
        (const float*)d_in[12], (const float*)d_in[13], (const float*)d_in[14],
        (const float*)d_in[15], (const float*)d_in[16], (const float*)d_in[17],
        (const float*)d_in[18], (const float*)d_in[19], (const float*)d_in[20],
        (const float*)d_in[21], (const float*)d_in[22], (const float*)d_in[23],
        (const float*)d_in[24], (const float*)d_in[25], (const float*)d_in[26]);

    main_kernel<<<2048, 512, SM_TOTAL>>>(
        (const float*)d_in[0], (const float*)d_in[1], (const float*)d_in[2], (float*)d_out);
}

// round 6
// speedup vs baseline: 1.2937x; 1.2937x over previous
#include <cuda_runtime.h>
#include <cuda_fp16.h>
#include <cstdint>
#include <math.h>

#define NPTS 8192
#define SSZ  1024
#define EPSF 1e-7f

__device__ __align__(16) float g_misc[2784];
__device__ __align__(16) uint2 g_bf1[4096];   // f1 B-fragments (fp16, unsplit)
__device__ __align__(16) uint2 g_bf2[8192];   // f2 B-fragments

#define MSF_W1T 0
#define MSF_B1  256
#define MSF_W2T 288
#define MSF_B2  2336
#define MSF_FB1 2400
#define MSF_FB2 2528

// smem byte offsets (R4 layout)
#define SM_MISC 0
#define SM_PART 11136
#define SM_A1H  19456
#define SM_A1L  54272
#define SM_A2H  89088
#define SM_A2L  123904
#define SM_TOTAL 158720
#define AST 68          // A-image row stride in words (conflict-free for ldmatrix)

__device__ __forceinline__ uint32_t pack_h(float a, float b) {
    __half2 h = __floats2half2_rn(a, b);
    return *(uint32_t*)&h;
}
__device__ __forceinline__ uint32_t pack_l(float a, float b) {
    float ra = a - __half2float(__float2half_rn(a));
    float rb = b - __half2float(__float2half_rn(b));
    return pack_h(ra, rb);
}
__device__ __forceinline__ uint32_t smem_u32(const void* p) {
    uint32_t a;
    asm("{ .reg .u64 t; cvta.to.shared.u64 t, %1; cvt.u32.u64 %0, t; }" : "=r"(a) : "l"(p));
    return a;
}
__device__ __forceinline__ void lda4(uint32_t r[4], uint32_t sbase, int rowbase, int s, int lane) {
    int row = rowbase + (lane & 7) + ((lane >> 3) & 1) * 8;
    int kw  = 8 * s + ((lane >> 4) << 2);
    uint32_t addr = sbase + (uint32_t)(row * (AST * 4) + kw * 4);
    asm volatile("ldmatrix.sync.aligned.m8n8.x4.shared.b16 {%0,%1,%2,%3}, [%4];"
        : "=r"(r[0]), "=r"(r[1]), "=r"(r[2]), "=r"(r[3]) : "r"(addr));
}
__device__ __forceinline__ void mma_f16(float* d, const uint32_t* a, uint32_t b0, uint32_t b1) {
    asm volatile("mma.sync.aligned.m16n8k16.row.col.f32.f16.f16.f32 "
        "{%0,%1,%2,%3}, {%4,%5,%6,%7}, {%8,%9}, {%0,%1,%2,%3};"
        : "+f"(d[0]), "+f"(d[1]), "+f"(d[2]), "+f"(d[3])
        : "r"(a[0]), "r"(a[1]), "r"(a[2]), "r"(a[3]), "r"(b0), "r"(b1));
}
__device__ __forceinline__ float clamp1(float x) {
    return fminf(fmaxf(x, -1.0f + EPSF), 1.0f - EPSF);
}

// ---------------- prep: fold BN, pack fp16 fragments ----------------
__global__ void prep_kernel(
    const float* __restrict__ ew1, const float* __restrict__ eb1, const float* __restrict__ eg1,
    const float* __restrict__ ebeta1, const float* __restrict__ em1, const float* __restrict__ ev1,
    const float* __restrict__ ew2, const float* __restrict__ eb2, const float* __restrict__ eg2,
    const float* __restrict__ ebeta2, const float* __restrict__ em2, const float* __restrict__ ev2,
    const float* __restrict__ fw1, const float* __restrict__ fb1, const float* __restrict__ fg1,
    const float* __restrict__ fbeta1, const float* __restrict__ fm1, const float* __restrict__ fv1,
    const float* __restrict__ fw2, const float* __restrict__ fb2, const float* __restrict__ fg2,
    const float* __restrict__ fbeta2, const float* __restrict__ fm2, const float* __restrict__ fv2)
{
    int t = blockIdx.x * blockDim.x + threadIdx.x;
    int stride = gridDim.x * blockDim.x;

    for (int i = t; i < 4096; i += stride) {
        int lane = i & 31, s = (i >> 5) & 7, nt = i >> 8;
        int n = nt * 8 + (lane >> 2);
        int k0 = s * 16 + (lane & 3) * 2;
        float sc = fg1[n] * rsqrtf(fv1[n] + 1e-5f);
        float v00 = fw1[n * 128 + k0] * sc,     v01 = fw1[n * 128 + k0 + 1] * sc;
        float v10 = fw1[n * 128 + k0 + 8] * sc, v11 = fw1[n * 128 + k0 + 9] * sc;
        uint2 r;
        r.x = pack_h(v00, v01); r.y = pack_h(v10, v11);
        g_bf1[i] = r;
    }
    for (int i = t; i < 8192; i += stride) {
        int lane = i & 31, s = (i >> 5) & 7, nt = i >> 8;
        int n = nt * 8 + (lane >> 2);
        int k0 = s * 16 + (lane & 3) * 2;
        float sc = fg2[n] * rsqrtf(fv2[n] + 1e-5f);
        float v00 = fw2[n * 128 + k0] * sc,     v01 = fw2[n * 128 + k0 + 1] * sc;
        float v10 = fw2[n * 128 + k0 + 8] * sc, v11 = fw2[n * 128 + k0 + 9] * sc;
        uint2 r;
        r.x = pack_h(v00, v01); r.y = pack_h(v10, v11);
        g_bf2[i] = r;
    }
    for (int i = t; i < 256; i += stride) {
        int o = i & 31, c = i >> 5;
        g_misc[MSF_W1T + c * 32 + o] = ew1[o * 8 + c] * (eg1[o] * rsqrtf(ev1[o] + 1e-5f));
    }
    for (int i = t; i < 32; i += stride) {
        float sc = eg1[i] * rsqrtf(ev1[i] + 1e-5f);
        g_misc[MSF_B1 + i] = (eb1[i] - em1[i]) * sc + ebeta1[i];
    }
    for (int i = t; i < 2048; i += stride) {
        int o = i & 63, c = i >> 6;
        g_misc[MSF_W2T + c * 64 + o] = ew2[o * 32 + c] * (eg2[o] * rsqrtf(ev2[o] + 1e-5f));
    }
    for (int i = t; i < 64; i += stride) {
        float sc = eg2[i] * rsqrtf(ev2[i] + 1e-5f);
        g_misc[MSF_B2 + i] = (eb2[i] - em2[i]) * sc + ebeta2[i];
    }
    for (int i = t; i < 128; i += stride) {
        float sc = fg1[i] * rsqrtf(fv1[i] + 1e-5f);
        g_misc[MSF_FB1 + i] = (fb1[i] - fm1[i]) * sc + fbeta1[i];
    }
    for (int i = t; i < 256; i += stride) {
        float sc = fg2[i] * rsqrtf(fv2[i] + 1e-5f);
        g_misc[MSF_FB2 + i] = (fb2[i] - fm2[i]) * sc + fbeta2[i];
    }
}

// ---------------- main kernel: 256 threads, 8 warps (R4 config) ----------------
__global__ __launch_bounds__(256, 1) void main_kernel(
    const float* __restrict__ contour,
    const float* __restrict__ loa,
    const float* __restrict__ prev,
    float* __restrict__ out)
{
    extern __shared__ char smem[];
    const uint32_t sb = smem_u32(smem);
    float* ms = (float*)(smem + SM_MISC);
    float* part = (float*)(smem + SM_PART);
    uint32_t* a1h = (uint32_t*)(smem + SM_A1H);
    uint32_t* a1l = (uint32_t*)(smem + SM_A1L);
    uint32_t* a2h = (uint32_t*)(smem + SM_A2H);
    uint32_t* a2l = (uint32_t*)(smem + SM_A2L);

    const int t = threadIdx.x;
    const int lane = t & 31;
    const int warp = t >> 5;
    const int b = blockIdx.x >> 8;
    const int s_base = (blockIdx.x & 255) * 4;

    // stage misc weights to smem
    {
        const uint4* src = (const uint4*)g_misc;
        uint4* dst = (uint4*)ms;
        for (int i = t; i < 696; i += 256) dst[i] = src[i];
    }

    // ---- geometry (per row; duplicated by both channel-halves) ----
    const int row = t & 127;
    const int ohalf = t >> 7;
    const int k = row & 31;
    const int s = s_base + (row >> 5);
    int nii;
    if (s == SSZ - 1) nii = NPTS - 1;
    else nii = (int)((double)s * ((double)(NPTS - 1) / (double)(SSZ - 1)));
    const int g  = (nii - 16 + k) & (NPTS - 1);
    const int gp = (nii - 16 + k - 1) & (NPTS - 1);

    float rif[8];
    {
        const float2* cptr = (const float2*)(contour + (size_t)b * NPTS * 2);
        const float2* lptr = (const float2*)(loa + (size_t)b * NPTS * 2);
        float2 xi = cptr[g], lxi = lptr[g];
        float2 xp = cptr[gp], lxp = lptr[gp];
        float2 ci = cptr[nii], lci = lptr[nii];

        float vx = xi.x - ci.x, vy = xi.y - ci.y;
        float f4 = sqrtf(vx * vx + vy * vy);
        float inv = 1.0f / (f4 + EPSF);
        float ux = vx * inv, uy = vy * inv;
        float a1 = lci.x * ux + lci.y * uy;
        float a2 = -(lxi.x * ux + lxi.y * uy);
        float f3 = ((a1 < a2) ? 1.0f : -1.0f) * acosf(clamp1(lxi.x * lci.x + lxi.y * lci.y));

        float vpx, vpy, lmx, lmy, rux, ruy;
        if (k > 0) {
            vpx = xi.x - xp.x; vpy = xi.y - xp.y;
            lmx = lxp.x;       lmy = lxp.y;
            float pvx = xp.x - ci.x, pvy = xp.y - ci.y;
            float invp = 1.0f / (sqrtf(pvx * pvx + pvy * pvy) + EPSF);
            rux = pvx * invp; ruy = pvy * invp;
        } else {
            vpx = vpy = lmx = lmy = rux = ruy = 0.0f;
        }
        float f8 = sqrtf(vpx * vpx + vpy * vpy);
        float inv8 = 1.0f / (f8 + EPSF);
        float upx = vpx * inv8, upy = vpy * inv8;
        float a4 = upx * lxi.x + upy * lxi.y;
        float a5 = upx * lmx + upy * lmy;
        float f7 = ((a4 < a5) ? 1.0f : -1.0f) * acosf(clamp1(lxi.x * lmx + lxi.y * lmy));
        float d2 = acosf(clamp1(ux * rux + uy * ruy));

        rif[0] = f4; rif[1] = d2; rif[2] = a1; rif[3] = a2;
        rif[4] = f3; rif[5] = a4; rif[6] = a5; rif[7] = f7;
    }
    __syncthreads();  // misc staged

    // ---- e1: 8 -> 32 ----
    float h1v[32];
    #pragma unroll
    for (int o4 = 0; o4 < 8; o4++) {
        float4 bb = *(const float4*)&ms[MSF_B1 + o4 * 4];
        h1v[o4 * 4 + 0] = bb.x; h1v[o4 * 4 + 1] = bb.y;
        h1v[o4 * 4 + 2] = bb.z; h1v[o4 * 4 + 3] = bb.w;
    }
    #pragma unroll
    for (int c = 0; c < 8; c++) {
        float rc = rif[c];
        #pragma unroll
        for (int o4 = 0; o4 < 8; o4++) {
            float4 w = *(const float4*)&ms[MSF_W1T + c * 32 + o4 * 4];
            h1v[o4 * 4 + 0] += w.x * rc; h1v[o4 * 4 + 1] += w.y * rc;
            h1v[o4 * 4 + 2] += w.z * rc; h1v[o4 * 4 + 3] += w.w * rc;
        }
    }
    #pragma unroll
    for (int o = 0; o < 32; o++) h1v[o] = fmaxf(h1v[o], 0.0f);

    // ---- e2: 32 -> 64 (this half's 32 channels) ----
    float acc2[32];
    {
        const int o0 = 32 * ohalf;
        #pragma unroll
        for (int j4 = 0; j4 < 8; j4++) {
            float4 bb = *(const float4*)&ms[MSF_B2 + o0 + j4 * 4];
            acc2[j4 * 4 + 0] = bb.x; acc2[j4 * 4 + 1] = bb.y;
            acc2[j4 * 4 + 2] = bb.z; acc2[j4 * 4 + 3] = bb.w;
        }
        #pragma unroll 4
        for (int c = 0; c < 32; c++) {
            float hc = h1v[c];
            #pragma unroll
            for (int j4 = 0; j4 < 8; j4++) {
                float4 w = *(const float4*)&ms[MSF_W2T + c * 64 + o0 + j4 * 4];
                acc2[j4 * 4 + 0] += w.x * hc; acc2[j4 * 4 + 1] += w.y * hc;
                acc2[j4 * 4 + 2] += w.z * hc; acc2[j4 * 4 + 3] += w.w * hc;
            }
        }
    }
    // e2 channels -> A1 words [row][16*ohalf + jp]
    #pragma unroll
    for (int jp = 0; jp < 16; jp++) {
        float v0 = fmaxf(acc2[2 * jp], 0.0f);
        float v1 = fmaxf(acc2[2 * jp + 1], 0.0f);
        int wi = row * AST + 16 * ohalf + jp;
        a1h[wi] = pack_h(v0, v1);
        a1l[wi] = pack_l(v0, v1);
    }
    // prev gather -> A1 words [row][32 + 16*ohalf + jp]
    {
        const float* pb = prev + ((size_t)b * 64 + 32 * (size_t)ohalf) * NPTS + g;
        #pragma unroll
        for (int jp = 0; jp < 16; jp++) {
            float v0 = pb[(size_t)(2 * jp) * NPTS];
            float v1 = pb[(size_t)(2 * jp + 1) * NPTS];
            int wi = row * AST + 32 + 16 * ohalf + jp;
            a1h[wi] = pack_h(v0, v1);
            a1l[wi] = pack_l(v0, v1);
        }
    }
    __syncthreads();

    const int mg = warp >> 2;       // 0..1 : rows 64*mg
    const int ng = warp & 3;        // 0..3
    const int jj = lane & 3;
    const int qq = lane >> 2;
    const uint32_t sbA1H = sb + SM_A1H, sbA1L = sb + SM_A1L;
    const uint32_t sbA2H = sb + SM_A2H, sbA2L = sb + SM_A2L;

    // ================= f1: 128 -> 128 =================
    {
        float acc[4][4][4];
        #pragma unroll
        for (int nt = 0; nt < 4; nt++) {
            int cb = (ng * 4 + nt) * 8 + 2 * jj;
            float be = ms[MSF_FB1 + cb], bo = ms[MSF_FB1 + cb + 1];
            #pragma unroll
            for (int mt = 0; mt < 4; mt++) {
                acc[mt][nt][0] = be; acc[mt][nt][1] = bo;
                acc[mt][nt][2] = be; acc[mt][nt][3] = bo;
            }
        }
        uint2 bcur[4];
        #pragma unroll
        for (int nt = 0; nt < 4; nt++)
            bcur[nt] = __ldg(&g_bf1[(ng * 4 + nt) * 256 + lane]);
        #pragma unroll
        for (int sstep = 0; sstep < 8; sstep++) {
            uint2 bnxt[4];
            if (sstep < 7) {
                #pragma unroll
                for (int nt = 0; nt < 4; nt++)
                    bnxt[nt] = __ldg(&g_bf1[(ng * 4 + nt) * 256 + (sstep + 1) * 32 + lane]);
            }
            #pragma unroll
            for (int mt = 0; mt < 4; mt++) {
                uint32_t a4[4];
                lda4(a4, sbA1H, mg * 64 + 16 * mt, sstep, lane);
                #pragma unroll
                for (int nt = 0; nt < 4; nt++)
                    mma_f16(acc[mt][nt], a4, bcur[nt].x, bcur[nt].y);
                lda4(a4, sbA1L, mg * 64 + 16 * mt, sstep, lane);
                #pragma unroll
                for (int nt = 0; nt < 4; nt++)
                    mma_f16(acc[mt][nt], a4, bcur[nt].x, bcur[nt].y);
            }
            if (sstep < 7) {
                #pragma unroll
                for (int nt = 0; nt < 4; nt++) bcur[nt] = bnxt[nt];
            }
        }
        // relu + split + store to A2
        #pragma unroll
        for (int mt = 0; mt < 4; mt++) {
            #pragma unroll
            for (int nt = 0; nt < 4; nt++) {
                int r0 = mg * 64 + 16 * mt + qq;
                int wi = (ng * 4 + nt) * 4 + jj;
                float v0 = fmaxf(acc[mt][nt][0], 0.0f), v1 = fmaxf(acc[mt][nt][1], 0.0f);
                a2h[r0 * AST + wi] = pack_h(v0, v1);
                a2l[r0 * AST + wi] = pack_l(v0, v1);
                float v2 = fmaxf(acc[mt][nt][2], 0.0f), v3 = fmaxf(acc[mt][nt][3], 0.0f);
                a2h[(r0 + 8) * AST + wi] = pack_h(v2, v3);
                a2l[(r0 + 8) * AST + wi] = pack_l(v2, v3);
            }
        }
    }
    __syncthreads();

    // ================= f2: 128 -> 256 (+ k-max) =================
    #pragma unroll 1
    for (int cnk = 0; cnk < 2; cnk++) {
        const int ntg0 = ng * 8 + cnk * 4;
        float acc[4][4][4];
        #pragma unroll
        for (int nt = 0; nt < 4; nt++) {
            int cb = (ntg0 + nt) * 8 + 2 * jj;
            float be = ms[MSF_FB2 + cb], bo = ms[MSF_FB2 + cb + 1];
            #pragma unroll
            for (int mt = 0; mt < 4; mt++) {
                acc[mt][nt][0] = be; acc[mt][nt][1] = bo;
                acc[mt][nt][2] = be; acc[mt][nt][3] = bo;
            }
        }
        uint2 bcur[4];
        #pragma unroll
        for (int nt = 0; nt < 4; nt++)
            bcur[nt] = __ldg(&g_bf2[(ntg0 + nt) * 256 + lane]);
        #pragma unroll
        for (int sstep = 0; sstep < 8; sstep++) {
            uint2 bnxt[4];
            if (sstep < 7) {
                #pragma unroll
                for (int nt = 0; nt < 4; nt++)
                    bnxt[nt] = __ldg(&g_bf2[(ntg0 + nt) * 256 + (sstep + 1) * 32 + lane]);
            }
            #pragma unroll
            for (int mt = 0; mt < 4; mt++) {
                uint32_t a4[4];
                lda4(a4, sbA2H, mg * 64 + 16 * mt, sstep, lane);
                #pragma unroll
                for (int nt = 0; nt < 4; nt++)
                    mma_f16(acc[mt][nt], a4, bcur[nt].x, bcur[nt].y);
                lda4(a4, sbA2L, mg * 64 + 16 * mt, sstep, lane);
                #pragma unroll
                for (int nt = 0; nt < 4; nt++)
                    mma_f16(acc[mt][nt], a4, bcur[nt].x, bcur[nt].y);
            }
            if (sstep < 7) {
                #pragma unroll
                for (int nt = 0; nt < 4; nt++) bcur[nt] = bnxt[nt];
            }
        }
        // relu + max over 16 rows + stage
        #pragma unroll
        for (int mt = 0; mt < 4; mt++) {
            const int sl = 2 * mg + (mt >> 1);
            const int kh = mt & 1;
            #pragma unroll
            for (int nt = 0; nt < 4; nt++) {
                float me = fmaxf(fmaxf(acc[mt][nt][0], acc[mt][nt][2]), 0.0f);
                float mo = fmaxf(fmaxf(acc[mt][nt][1], acc[mt][nt][3]), 0.0f);
                me = fmaxf(me, __shfl_xor_sync(0xffffffffu, me, 4));
                me = fmaxf(me, __shfl_xor_sync(0xffffffffu, me, 8));
                me = fmaxf(me, __shfl_xor_sync(0xffffffffu, me, 16));
                mo = fmaxf(mo, __shfl_xor_sync(0xffffffffu, mo, 4));
                mo = fmaxf(mo, __shfl_xor_sync(0xffffffffu, mo, 8));
                mo = fmaxf(mo, __shfl_xor_sync(0xffffffffu, mo, 16));
                if (lane < 4) {
                    int col = (ntg0 + nt) * 8 + 2 * lane;
                    part[sl * 512 + kh * 256 + col] = me;
                    part[sl * 512 + kh * 256 + col + 1] = mo;
                }
            }
        }
    }
    __syncthreads();

    // ---- final: combine k-halves, coalesced store ----
    {
        float4 v;
        v.x = fmaxf(part[0 * 512 + t], part[0 * 512 + 256 + t]);
        v.y = fmaxf(part[1 * 512 + t], part[1 * 512 + 256 + t]);
        v.z = fmaxf(part[2 * 512 + t], part[2 * 512 + 256 + t]);
        v.w = fmaxf(part[3 * 512 + t], part[3 * 512 + 256 + t]);
        *(float4*)(out + ((size_t)(b * 256 + t)) * SSZ + s_base) = v;
    }
}

extern "C" void kernel_launch(void* const* d_in, const int* in_sizes, int n_in,
                              void* d_out, int out_size)
{
    cudaFuncSetAttribute(main_kernel, cudaFuncAttributeMaxDynamicSharedMemorySize, SM_TOTAL);

    prep_kernel<<<64, 256>>>(
        (const float*)d_in[3],  (const float*)d_in[4],  (const float*)d_in[5],
        (const float*)d_in[6],  (const float*)d_in[7],  (const float*)d_in[8],
        (const float*)d_in[9],  (const float*)d_in[10], (const float*)d_in[11],
        (const float*)d_in[12], (const float*)d_in[13], (const float*)d_in[14],
        (const float*)d_in[15], (const float*)d_in[16], (const float*)d_in[17],
        (const float*)d_in[18], (const float*)d_in[19], (const float*)d_in[20],
        (const float*)d_in[21], (const float*)d_in[22], (const float*)d_in[23],
        (const float*)d_in[24], (const float*)d_in[25], (const float*)d_in[26]);

    main_kernel<<<2048, 256, SM_TOTAL>>>(
        (const float*)d_in[0], (const float*)d_in[1], (const float*)d_in[2], (float*)d_out);
}

// round 7
// speedup vs baseline: 1.7039x; 1.3171x over previous
#include <cuda_runtime.h>
#include <cuda_fp16.h>
#include <cstdint>
#include <math.h>

#define NPTS 8192
#define SSZ  1024
#define EPSF 1e-7f

__device__ __align__(16) float g_misc[2784];
__device__ __align__(16) uint2 g_bf1[4096];   // f1 B-fragments (fp16, unsplit)
__device__ __align__(16) uint2 g_bf2[8192];   // f2 B-fragments

#define MSF_W1T 0
#define MSF_B1  256
#define MSF_W2T 288
#define MSF_B2  2336
#define MSF_FB1 2400
#define MSF_FB2 2528

// smem byte offsets — single A image reused by f1 and f2
#define SM_MISC 0
#define SM_PART 11136
#define SM_AH   19456
#define SM_AL   54272
#define SM_TOTAL 89088
#define AST 68          // A-image row stride in words (conflict-free for ldmatrix)

__device__ __forceinline__ uint32_t pack_h(float a, float b) {
    __half2 h = __floats2half2_rn(a, b);
    return *(uint32_t*)&h;
}
__device__ __forceinline__ uint32_t pack_l(float a, float b) {
    float ra = a - __half2float(__float2half_rn(a));
    float rb = b - __half2float(__float2half_rn(b));
    return pack_h(ra, rb);
}
__device__ __forceinline__ uint32_t smem_u32(const void* p) {
    uint32_t a;
    asm("{ .reg .u64 t; cvta.to.shared.u64 t, %1; cvt.u32.u64 %0, t; }" : "=r"(a) : "l"(p));
    return a;
}
__device__ __forceinline__ void lda4(uint32_t r[4], uint32_t sbase, int rowbase, int s, int lane) {
    int row = rowbase + (lane & 7) + ((lane >> 3) & 1) * 8;
    int kw  = 8 * s + ((lane >> 4) << 2);
    uint32_t addr = sbase + (uint32_t)(row * (AST * 4) + kw * 4);
    asm volatile("ldmatrix.sync.aligned.m8n8.x4.shared.b16 {%0,%1,%2,%3}, [%4];"
        : "=r"(r[0]), "=r"(r[1]), "=r"(r[2]), "=r"(r[3]) : "r"(addr));
}
__device__ __forceinline__ void mma_f16(float* d, const uint32_t* a, uint32_t b0, uint32_t b1) {
    asm volatile("mma.sync.aligned.m16n8k16.row.col.f32.f16.f16.f32 "
        "{%0,%1,%2,%3}, {%4,%5,%6,%7}, {%8,%9}, {%0,%1,%2,%3};"
        : "+f"(d[0]), "+f"(d[1]), "+f"(d[2]), "+f"(d[3])
        : "r"(a[0]), "r"(a[1]), "r"(a[2]), "r"(a[3]), "r"(b0), "r"(b1));
}
__device__ __forceinline__ float clamp1(float x) {
    return fminf(fmaxf(x, -1.0f + EPSF), 1.0f - EPSF);
}

// ---------------- prep: fold BN, pack fp16 fragments ----------------
__global__ void prep_kernel(
    const float* __restrict__ ew1, const float* __restrict__ eb1, const float* __restrict__ eg1,
    const float* __restrict__ ebeta1, const float* __restrict__ em1, const float* __restrict__ ev1,
    const float* __restrict__ ew2, const float* __restrict__ eb2, const float* __restrict__ eg2,
    const float* __restrict__ ebeta2, const float* __restrict__ em2, const float* __restrict__ ev2,
    const float* __restrict__ fw1, const float* __restrict__ fb1, const float* __restrict__ fg1,
    const float* __restrict__ fbeta1, const float* __restrict__ fm1, const float* __restrict__ fv1,
    const float* __restrict__ fw2, const float* __restrict__ fb2, const float* __restrict__ fg2,
    const float* __restrict__ fbeta2, const float* __restrict__ fm2, const float* __restrict__ fv2)
{
    int t = blockIdx.x * blockDim.x + threadIdx.x;
    int stride = gridDim.x * blockDim.x;

    for (int i = t; i < 4096; i += stride) {
        int lane = i & 31, s = (i >> 5) & 7, nt = i >> 8;
        int n = nt * 8 + (lane >> 2);
        int k0 = s * 16 + (lane & 3) * 2;
        float sc = fg1[n] * rsqrtf(fv1[n] + 1e-5f);
        float v00 = fw1[n * 128 + k0] * sc,     v01 = fw1[n * 128 + k0 + 1] * sc;
        float v10 = fw1[n * 128 + k0 + 8] * sc, v11 = fw1[n * 128 + k0 + 9] * sc;
        uint2 r;
        r.x = pack_h(v00, v01); r.y = pack_h(v10, v11);
        g_bf1[i] = r;
    }
    for (int i = t; i < 8192; i += stride) {
        int lane = i & 31, s = (i >> 5) & 7, nt = i >> 8;
        int n = nt * 8 + (lane >> 2);
        int k0 = s * 16 + (lane & 3) * 2;
        float sc = fg2[n] * rsqrtf(fv2[n] + 1e-5f);
        float v00 = fw2[n * 128 + k0] * sc,     v01 = fw2[n * 128 + k0 + 1] * sc;
        float v10 = fw2[n * 128 + k0 + 8] * sc, v11 = fw2[n * 128 + k0 + 9] * sc;
        uint2 r;
        r.x = pack_h(v00, v01); r.y = pack_h(v10, v11);
        g_bf2[i] = r;
    }
    for (int i = t; i < 256; i += stride) {
        int o = i & 31, c = i >> 5;
        g_misc[MSF_W1T + c * 32 + o] = ew1[o * 8 + c] * (eg1[o] * rsqrtf(ev1[o] + 1e-5f));
    }
    for (int i = t; i < 32; i += stride) {
        float sc = eg1[i] * rsqrtf(ev1[i] + 1e-5f);
        g_misc[MSF_B1 + i] = (eb1[i] - em1[i]) * sc + ebeta1[i];
    }
    for (int i = t; i < 2048; i += stride) {
        int o = i & 63, c = i >> 6;
        g_misc[MSF_W2T + c * 64 + o] = ew2[o * 32 + c] * (eg2[o] * rsqrtf(ev2[o] + 1e-5f));
    }
    for (int i = t; i < 64; i += stride) {
        float sc = eg2[i] * rsqrtf(ev2[i] + 1e-5f);
        g_misc[MSF_B2 + i] = (eb2[i] - em2[i]) * sc + ebeta2[i];
    }
    for (int i = t; i < 128; i += stride) {
        float sc = fg1[i] * rsqrtf(fv1[i] + 1e-5f);
        g_misc[MSF_FB1 + i] = (fb1[i] - fm1[i]) * sc + fbeta1[i];
    }
    for (int i = t; i < 256; i += stride) {
        float sc = fg2[i] * rsqrtf(fv2[i] + 1e-5f);
        g_misc[MSF_FB2 + i] = (fb2[i] - fm2[i]) * sc + fbeta2[i];
    }
}

// ---------------- main kernel: 256 threads, 8 warps, 2 CTAs/SM ----------------
__global__ __launch_bounds__(256, 2) void main_kernel(
    const float* __restrict__ contour,
    const float* __restrict__ loa,
    const float* __restrict__ prev,
    float* __restrict__ out)
{
    extern __shared__ char smem[];
    const uint32_t sb = smem_u32(smem);
    float* ms = (float*)(smem + SM_MISC);
    float* part = (float*)(smem + SM_PART);
    uint32_t* ah = (uint32_t*)(smem + SM_AH);
    uint32_t* al = (uint32_t*)(smem + SM_AL);

    const int t = threadIdx.x;
    const int lane = t & 31;
    const int warp = t >> 5;
    const int b = blockIdx.x >> 8;
    const int s_base = (blockIdx.x & 255) * 4;

    // stage misc weights to smem
    {
        const uint4* src = (const uint4*)g_misc;
        uint4* dst = (uint4*)ms;
        for (int i = t; i < 696; i += 256) dst[i] = src[i];
    }

    // ---- geometry (per row; duplicated by both channel-halves) ----
    const int row = t & 127;
    const int ohalf = t >> 7;
    const int k = row & 31;
    const int s = s_base + (row >> 5);
    const int nii = (int)(((long long)s * (NPTS - 1)) / (SSZ - 1));
    const int g  = (nii - 16 + k) & (NPTS - 1);
    const int gp = (nii - 16 + k - 1) & (NPTS - 1);

    float rif[8];
    {
        const float2* cptr = (const float2*)(contour + (size_t)b * NPTS * 2);
        const float2* lptr = (const float2*)(loa + (size_t)b * NPTS * 2);
        float2 xi = cptr[g], lxi = lptr[g];
        float2 xp = cptr[gp], lxp = lptr[gp];
        float2 ci = cptr[nii], lci = lptr[nii];

        float vx = xi.x - ci.x, vy = xi.y - ci.y;
        float f4 = sqrtf(vx * vx + vy * vy);
        float inv = 1.0f / (f4 + EPSF);
        float ux = vx * inv, uy = vy * inv;
        float a1 = lci.x * ux + lci.y * uy;
        float a2 = -(lxi.x * ux + lxi.y * uy);
        float f3 = ((a1 < a2) ? 1.0f : -1.0f) * acosf(clamp1(lxi.x * lci.x + lxi.y * lci.y));

        float vpx, vpy, lmx, lmy, rux, ruy;
        if (k > 0) {
            vpx = xi.x - xp.x; vpy = xi.y - xp.y;
            lmx = lxp.x;       lmy = lxp.y;
            float pvx = xp.x - ci.x, pvy = xp.y - ci.y;
            float invp = 1.0f / (sqrtf(pvx * pvx + pvy * pvy) + EPSF);
            rux = pvx * invp; ruy = pvy * invp;
        } else {
            vpx = vpy = lmx = lmy = rux = ruy = 0.0f;
        }
        float f8 = sqrtf(vpx * vpx + vpy * vpy);
        float inv8 = 1.0f / (f8 + EPSF);
        float upx = vpx * inv8, upy = vpy * inv8;
        float a4 = upx * lxi.x + upy * lxi.y;
        float a5 = upx * lmx + upy * lmy;
        float f7 = ((a4 < a5) ? 1.0f : -1.0f) * acosf(clamp1(lxi.x * lmx + lxi.y * lmy));
        float d2 = acosf(clamp1(ux * rux + uy * ruy));

        rif[0] = f4; rif[1] = d2; rif[2] = a1; rif[3] = a2;
        rif[4] = f3; rif[5] = a4; rif[6] = a5; rif[7] = f7;
    }
    __syncthreads();  // misc staged

    // ---- e1: 8 -> 32 ----
    float h1v[32];
    #pragma unroll
    for (int o4 = 0; o4 < 8; o4++) {
        float4 bb = *(const float4*)&ms[MSF_B1 + o4 * 4];
        h1v[o4 * 4 + 0] = bb.x; h1v[o4 * 4 + 1] = bb.y;
        h1v[o4 * 4 + 2] = bb.z; h1v[o4 * 4 + 3] = bb.w;
    }
    #pragma unroll
    for (int c = 0; c < 8; c++) {
        float rc = rif[c];
        #pragma unroll
        for (int o4 = 0; o4 < 8; o4++) {
            float4 w = *(const float4*)&ms[MSF_W1T + c * 32 + o4 * 4];
            h1v[o4 * 4 + 0] += w.x * rc; h1v[o4 * 4 + 1] += w.y * rc;
            h1v[o4 * 4 + 2] += w.z * rc; h1v[o4 * 4 + 3] += w.w * rc;
        }
    }
    #pragma unroll
    for (int o = 0; o < 32; o++) h1v[o] = fmaxf(h1v[o], 0.0f);

    // ---- e2: 32 -> 64 (this half's 32 channels) ----
    float acc2[32];
    {
        const int o0 = 32 * ohalf;
        #pragma unroll
        for (int j4 = 0; j4 < 8; j4++) {
            float4 bb = *(const float4*)&ms[MSF_B2 + o0 + j4 * 4];
            acc2[j4 * 4 + 0] = bb.x; acc2[j4 * 4 + 1] = bb.y;
            acc2[j4 * 4 + 2] = bb.z; acc2[j4 * 4 + 3] = bb.w;
        }
        #pragma unroll 4
        for (int c = 0; c < 32; c++) {
            float hc = h1v[c];
            #pragma unroll
            for (int j4 = 0; j4 < 8; j4++) {
                float4 w = *(const float4*)&ms[MSF_W2T + c * 64 + o0 + j4 * 4];
                acc2[j4 * 4 + 0] += w.x * hc; acc2[j4 * 4 + 1] += w.y * hc;
                acc2[j4 * 4 + 2] += w.z * hc; acc2[j4 * 4 + 3] += w.w * hc;
            }
        }
    }
    // e2 channels -> A words [row][16*ohalf + jp]
    #pragma unroll
    for (int jp = 0; jp < 16; jp++) {
        float v0 = fmaxf(acc2[2 * jp], 0.0f);
        float v1 = fmaxf(acc2[2 * jp + 1], 0.0f);
        int wi = row * AST + 16 * ohalf + jp;
        ah[wi] = pack_h(v0, v1);
        al[wi] = pack_l(v0, v1);
    }
    // prev gather -> A words [row][32 + 16*ohalf + jp]
    {
        const float* pb = prev + ((size_t)b * 64 + 32 * (size_t)ohalf) * NPTS + g;
        #pragma unroll
        for (int jp = 0; jp < 16; jp++) {
            float v0 = pb[(size_t)(2 * jp) * NPTS];
            float v1 = pb[(size_t)(2 * jp + 1) * NPTS];
            int wi = row * AST + 32 + 16 * ohalf + jp;
            ah[wi] = pack_h(v0, v1);
            al[wi] = pack_l(v0, v1);
        }
    }
    __syncthreads();

    const int mg = warp >> 2;       // 0..1 : rows 64*mg
    const int ng = warp & 3;        // 0..3
    const int jj = lane & 3;
    const int qq = lane >> 2;
    const uint32_t sbAH = sb + SM_AH, sbAL = sb + SM_AL;

    // ================= f1: 128 -> 128 (acc in regs; A reused after sync) =================
    float acc[4][4][4];
    {
        #pragma unroll
        for (int nt = 0; nt < 4; nt++) {
            int cb = (ng * 4 + nt) * 8 + 2 * jj;
            float be = ms[MSF_FB1 + cb], bo = ms[MSF_FB1 + cb + 1];
            #pragma unroll
            for (int mt = 0; mt < 4; mt++) {
                acc[mt][nt][0] = be; acc[mt][nt][1] = bo;
                acc[mt][nt][2] = be; acc[mt][nt][3] = bo;
            }
        }
        uint2 bcur[4];
        #pragma unroll
        for (int nt = 0; nt < 4; nt++)
            bcur[nt] = __ldg(&g_bf1[(ng * 4 + nt) * 256 + lane]);
        #pragma unroll
        for (int sstep = 0; sstep < 8; sstep++) {
            uint2 bnxt[4];
            if (sstep < 7) {
                #pragma unroll
                for (int nt = 0; nt < 4; nt++)
                    bnxt[nt] = __ldg(&g_bf1[(ng * 4 + nt) * 256 + (sstep + 1) * 32 + lane]);
            }
            #pragma unroll
            for (int mt = 0; mt < 4; mt++) {
                uint32_t a4[4];
                lda4(a4, sbAH, mg * 64 + 16 * mt, sstep, lane);
                #pragma unroll
                for (int nt = 0; nt < 4; nt++)
                    mma_f16(acc[mt][nt], a4, bcur[nt].x, bcur[nt].y);
                lda4(a4, sbAL, mg * 64 + 16 * mt, sstep, lane);
                #pragma unroll
                for (int nt = 0; nt < 4; nt++)
                    mma_f16(acc[mt][nt], a4, bcur[nt].x, bcur[nt].y);
            }
            if (sstep < 7) {
                #pragma unroll
                for (int nt = 0; nt < 4; nt++) bcur[nt] = bnxt[nt];
            }
        }
    }
    __syncthreads();   // all f1 reads of A complete — safe to overwrite

    // relu + split + store f1 outputs into the SAME A image
    #pragma unroll
    for (int mt = 0; mt < 4; mt++) {
        #pragma unroll
        for (int nt = 0; nt < 4; nt++) {
            int r0 = mg * 64 + 16 * mt + qq;
            int wi = (ng * 4 + nt) * 4 + jj;
            float v0 = fmaxf(acc[mt][nt][0], 0.0f), v1 = fmaxf(acc[mt][nt][1], 0.0f);
            ah[r0 * AST + wi] = pack_h(v0, v1);
            al[r0 * AST + wi] = pack_l(v0, v1);
            float v2 = fmaxf(acc[mt][nt][2], 0.0f), v3 = fmaxf(acc[mt][nt][3], 0.0f);
            ah[(r0 + 8) * AST + wi] = pack_h(v2, v3);
            al[(r0 + 8) * AST + wi] = pack_l(v2, v3);
        }
    }
    __syncthreads();

    // ================= f2: 128 -> 256 (+ k-max) =================
    #pragma unroll 1
    for (int cnk = 0; cnk < 2; cnk++) {
        const int ntg0 = ng * 8 + cnk * 4;
        #pragma unroll
        for (int nt = 0; nt < 4; nt++) {
            int cb = (ntg0 + nt) * 8 + 2 * jj;
            float be = ms[MSF_FB2 + cb], bo = ms[MSF_FB2 + cb + 1];
            #pragma unroll
            for (int mt = 0; mt < 4; mt++) {
                acc[mt][nt][0] = be; acc[mt][nt][1] = bo;
                acc[mt][nt][2] = be; acc[mt][nt][3] = bo;
            }
        }
        uint2 bcur[4];
        #pragma unroll
        for (int nt = 0; nt < 4; nt++)
            bcur[nt] = __ldg(&g_bf2[(ntg0 + nt) * 256 + lane]);
        #pragma unroll
        for (int sstep = 0; sstep < 8; sstep++) {
            uint2 bnxt[4];
            if (sstep < 7) {
                #pragma unroll
                for (int nt = 0; nt < 4; nt++)
                    bnxt[nt] = __ldg(&g_bf2[(ntg0 + nt) * 256 + (sstep + 1) * 32 + lane]);
            }
            #pragma unroll
            for (int mt = 0; mt < 4; mt++) {
                uint32_t a4[4];
                lda4(a4, sbAH, mg * 64 + 16 * mt, sstep, lane);
                #pragma unroll
                for (int nt = 0; nt < 4; nt++)
                    mma_f16(acc[mt][nt], a4, bcur[nt].x, bcur[nt].y);
                lda4(a4, sbAL, mg * 64 + 16 * mt, sstep, lane);
                #pragma unroll
                for (int nt = 0; nt < 4; nt++)
                    mma_f16(acc[mt][nt], a4, bcur[nt].x, bcur[nt].y);
            }
            if (sstep < 7) {
                #pragma unroll
                for (int nt = 0; nt < 4; nt++) bcur[nt] = bnxt[nt];
            }
        }
        // relu + max over 16 rows + stage
        #pragma unroll
        for (int mt = 0; mt < 4; mt++) {
            const int sl = 2 * mg + (mt >> 1);
            const int kh = mt & 1;
            #pragma unroll
            for (int nt = 0; nt < 4; nt++) {
                float me = fmaxf(fmaxf(acc[mt][nt][0], acc[mt][nt][2]), 0.0f);
                float mo = fmaxf(fmaxf(acc[mt][nt][1], acc[mt][nt][3]), 0.0f);
                me = fmaxf(me, __shfl_xor_sync(0xffffffffu, me, 4));
                me = fmaxf(me, __shfl_xor_sync(0xffffffffu, me, 8));
                me = fmaxf(me, __shfl_xor_sync(0xffffffffu, me, 16));
                mo = fmaxf(mo, __shfl_xor_sync(0xffffffffu, mo, 4));
                mo = fmaxf(mo, __shfl_xor_sync(0xffffffffu, mo, 8));
                mo = fmaxf(mo, __shfl_xor_sync(0xffffffffu, mo, 16));
                if (lane < 4) {
                    int col = (ntg0 + nt) * 8 + 2 * lane;
                    part[sl * 512 + kh * 256 + col] = me;
                    part[sl * 512 + kh * 256 + col + 1] = mo;
                }
            }
        }
    }
    __syncthreads();

    // ---- final: combine k-halves, coalesced store ----
    {
        float4 v;
        v.x = fmaxf(part[0 * 512 + t], part[0 * 512 + 256 + t]);
        v.y = fmaxf(part[1 * 512 + t], part[1 * 512 + 256 + t]);
        v.z = fmaxf(part[2 * 512 + t], part[2 * 512 + 256 + t]);
        v.w = fmaxf(part[3 * 512 + t], part[3 * 512 + 256 + t]);
        *(float4*)(out + ((size_t)(b * 256 + t)) * SSZ + s_base) = v;
    }
}

extern "C" void kernel_launch(void* const* d_in, const int* in_sizes, int n_in,
                              void* d_out, int out_size)
{
    cudaFuncSetAttribute(main_kernel, cudaFuncAttributeMaxDynamicSharedMemorySize, SM_TOTAL);

    prep_kernel<<<64, 256>>>(
        (const float*)d_in[3],  (const float*)d_in[4],  (const float*)d_in[5],
        (const float*)d_in[6],  (const float*)d_in[7],  (const float*)d_in[8],
        (const float*)d_in[9],  (const float*)d_in[10], (const float*)d_in[11],
        (const float*)d_in[12], (const float*)d_in[13], (const float*)d_in[14],
        (const float*)d_in[15], (const float*)d_in[16], (const float*)d_in[17],
        (const float*)d_in[18], (const float*)d_in[19], (const float*)d_in[20],
        (const float*)d_in[21], (const float*)d_in[22], (const float*)d_in[23],
        (const float*)d_in[24], (const float*)d_in[25], (const float*)d_in[26]);

    main_kernel<<<2048, 256, SM_TOTAL>>>(
        (const float*)d_in[0], (const float*)d_in[1], (const float*)d_in[2], (float*)d_out);
}

// round 9
// speedup vs baseline: 2.1799x; 1.2794x over previous
#include <cuda_runtime.h>
#include <cuda_fp16.h>
#include <cstdint>
#include <math.h>

#define NPTS 8192
#define SSZ  1024
#define EPSF 1e-7f

__device__ __align__(16) float g_misc[2784];
__device__ __align__(16) uint2 g_bf1[4096];   // f1 B-fragments (fp16)
__device__ __align__(16) uint2 g_bf2[8192];   // f2 B-fragments

#define MSF_W1T 0
#define MSF_B1  256
#define MSF_W2T 288
#define MSF_B2  2336
#define MSF_FB1 2400
#define MSF_FB2 2528

// smem byte offsets — single fp16 A image (no lo), reused by f1 and f2
#define SM_MISC 0
#define SM_PART 11136
#define SM_AH   19456
#define SM_TOTAL 54272
#define AST 68          // A-image row stride in words (conflict-free for ldmatrix)

__device__ __forceinline__ uint32_t pack_h(float a, float b) {
    __half2 h = __floats2half2_rn(a, b);
    return *(uint32_t*)&h;
}
__device__ __forceinline__ uint32_t smem_u32(const void* p) {
    uint32_t a;
    asm("{ .reg .u64 t; cvta.to.shared.u64 t, %1; cvt.u32.u64 %0, t; }" : "=r"(a) : "l"(p));
    return a;
}
__device__ __forceinline__ void lda4(uint32_t r[4], uint32_t sbase, int rowbase, int s, int lane) {
    int row = rowbase + (lane & 7) + ((lane >> 3) & 1) * 8;
    int kw  = 8 * s + ((lane >> 4) << 2);
    uint32_t addr = sbase + (uint32_t)(row * (AST * 4) + kw * 4);
    asm volatile("ldmatrix.sync.aligned.m8n8.x4.shared.b16 {%0,%1,%2,%3}, [%4];"
        : "=r"(r[0]), "=r"(r[1]), "=r"(r[2]), "=r"(r[3]) : "r"(addr));
}
__device__ __forceinline__ void mma_f16(float* d, const uint32_t* a, uint32_t b0, uint32_t b1) {
    asm volatile("mma.sync.aligned.m16n8k16.row.col.f32.f16.f16.f32 "
        "{%0,%1,%2,%3}, {%4,%5,%6,%7}, {%8,%9}, {%0,%1,%2,%3};"
        : "+f"(d[0]), "+f"(d[1]), "+f"(d[2]), "+f"(d[3])
        : "r"(a[0]), "r"(a[1]), "r"(a[2]), "r"(a[3]), "r"(b0), "r"(b1));
}
__device__ __forceinline__ float clamp1(float x) {
    return fminf(fmaxf(x, -1.0f + EPSF), 1.0f - EPSF);
}

// ---------------- prep: fold BN, pack fp16 fragments ----------------
__global__ void prep_kernel(
    const float* __restrict__ ew1, const float* __restrict__ eb1, const float* __restrict__ eg1,
    const float* __restrict__ ebeta1, const float* __restrict__ em1, const float* __restrict__ ev1,
    const float* __restrict__ ew2, const float* __restrict__ eb2, const float* __restrict__ eg2,
    const float* __restrict__ ebeta2, const float* __restrict__ em2, const float* __restrict__ ev2,
    const float* __restrict__ fw1, const float* __restrict__ fb1, const float* __restrict__ fg1,
    const float* __restrict__ fbeta1, const float* __restrict__ fm1, const float* __restrict__ fv1,
    const float* __restrict__ fw2, const float* __restrict__ fb2, const float* __restrict__ fg2,
    const float* __restrict__ fbeta2, const float* __restrict__ fm2, const float* __restrict__ fv2)
{
    int t = blockIdx.x * blockDim.x + threadIdx.x;
    int stride = gridDim.x * blockDim.x;

    for (int i = t; i < 4096; i += stride) {
        int lane = i & 31, s = (i >> 5) & 7, nt = i >> 8;
        int n = nt * 8 + (lane >> 2);
        int k0 = s * 16 + (lane & 3) * 2;
        float sc = fg1[n] * rsqrtf(fv1[n] + 1e-5f);
        float v00 = fw1[n * 128 + k0] * sc,     v01 = fw1[n * 128 + k0 + 1] * sc;
        float v10 = fw1[n * 128 + k0 + 8] * sc, v11 = fw1[n * 128 + k0 + 9] * sc;
        uint2 r;
        r.x = pack_h(v00, v01); r.y = pack_h(v10, v11);
        g_bf1[i] = r;
    }
    for (int i = t; i < 8192; i += stride) {
        int lane = i & 31, s = (i >> 5) & 7, nt = i >> 8;
        int n = nt * 8 + (lane >> 2);
        int k0 = s * 16 + (lane & 3) * 2;
        float sc = fg2[n] * rsqrtf(fv2[n] + 1e-5f);
        float v00 = fw2[n * 128 + k0] * sc,     v01 = fw2[n * 128 + k0 + 1] * sc;
        float v10 = fw2[n * 128 + k0 + 8] * sc, v11 = fw2[n * 128 + k0 + 9] * sc;
        uint2 r;
        r.x = pack_h(v00, v01); r.y = pack_h(v10, v11);
        g_bf2[i] = r;
    }
    for (int i = t; i < 256; i += stride) {
        int o = i & 31, c = i >> 5;
        g_misc[MSF_W1T + c * 32 + o] = ew1[o * 8 + c] * (eg1[o] * rsqrtf(ev1[o] + 1e-5f));
    }
    for (int i = t; i < 32; i += stride) {
        float sc = eg1[i] * rsqrtf(ev1[i] + 1e-5f);
        g_misc[MSF_B1 + i] = (eb1[i] - em1[i]) * sc + ebeta1[i];
    }
    for (int i = t; i < 2048; i += stride) {
        int o = i & 63, c = i >> 6;
        g_misc[MSF_W2T + c * 64 + o] = ew2[o * 32 + c] * (eg2[o] * rsqrtf(ev2[o] + 1e-5f));
    }
    for (int i = t; i < 64; i += stride) {
        float sc = eg2[i] * rsqrtf(ev2[i] + 1e-5f);
        g_misc[MSF_B2 + i] = (eb2[i] - em2[i]) * sc + ebeta2[i];
    }
    for (int i = t; i < 128; i += stride) {
        float sc = fg1[i] * rsqrtf(fv1[i] + 1e-5f);
        g_misc[MSF_FB1 + i] = (fb1[i] - fm1[i]) * sc + fbeta1[i];
    }
    for (int i = t; i < 256; i += stride) {
        float sc = fg2[i] * rsqrtf(fv2[i] + 1e-5f);
        g_misc[MSF_FB2 + i] = (fb2[i] - fm2[i]) * sc + fbeta2[i];
    }
}

// ---------------- main kernel: 256 threads, 8 warps, 2 CTAs/SM ----------------
__global__ __launch_bounds__(256, 2) void main_kernel(
    const float* __restrict__ contour,
    const float* __restrict__ loa,
    const float* __restrict__ prev,
    float* __restrict__ out)
{
    extern __shared__ char smem[];
    const uint32_t sb = smem_u32(smem);
    float* ms = (float*)(smem + SM_MISC);
    float* part = (float*)(smem + SM_PART);
    uint32_t* ah = (uint32_t*)(smem + SM_AH);

    const int t = threadIdx.x;
    const int lane = t & 31;
    const int warp = t >> 5;
    const int b = blockIdx.x >> 8;
    const int s_base = (blockIdx.x & 255) * 4;

    // stage misc weights to smem
    {
        const uint4* src = (const uint4*)g_misc;
        uint4* dst = (uint4*)ms;
        for (int i = t; i < 696; i += 256) dst[i] = src[i];
    }

    // ---- geometry (per row; duplicated by both channel-halves) ----
    const int row = t & 127;
    const int ohalf = t >> 7;
    const int k = row & 31;
    const int s = s_base + (row >> 5);
    const int nii = (int)(((long long)s * (NPTS - 1)) / (SSZ - 1));
    const int g  = (nii - 16 + k) & (NPTS - 1);
    const int gp = (nii - 16 + k - 1) & (NPTS - 1);

    float rif[8];
    {
        const float2* cptr = (const float2*)(contour + (size_t)b * NPTS * 2);
        const float2* lptr = (const float2*)(loa + (size_t)b * NPTS * 2);
        float2 xi = cptr[g], lxi = lptr[g];
        float2 xp = cptr[gp], lxp = lptr[gp];
        float2 ci = cptr[nii], lci = lptr[nii];

        float vx = xi.x - ci.x, vy = xi.y - ci.y;
        float f4 = sqrtf(vx * vx + vy * vy);
        float inv = 1.0f / (f4 + EPSF);
        float ux = vx * inv, uy = vy * inv;
        float a1 = lci.x * ux + lci.y * uy;
        float a2 = -(lxi.x * ux + lxi.y * uy);
        float f3 = ((a1 < a2) ? 1.0f : -1.0f) * acosf(clamp1(lxi.x * lci.x + lxi.y * lci.y));

        float vpx, vpy, lmx, lmy, rux, ruy;
        if (k > 0) {
            vpx = xi.x - xp.x; vpy = xi.y - xp.y;
            lmx = lxp.x;       lmy = lxp.y;
            float pvx = xp.x - ci.x, pvy = xp.y - ci.y;
            float invp = 1.0f / (sqrtf(pvx * pvx + pvy * pvy) + EPSF);
            rux = pvx * invp; ruy = pvy * invp;
        } else {
            vpx = vpy = lmx = lmy = rux = ruy = 0.0f;
        }
        float f8 = sqrtf(vpx * vpx + vpy * vpy);
        float inv8 = 1.0f / (f8 + EPSF);
        float upx = vpx * inv8, upy = vpy * inv8;
        float a4 = upx * lxi.x + upy * lxi.y;
        float a5 = upx * lmx + upy * lmy;
        float f7 = ((a4 < a5) ? 1.0f : -1.0f) * acosf(clamp1(lxi.x * lmx + lxi.y * lmy));
        float d2 = acosf(clamp1(ux * rux + uy * ruy));

        rif[0] = f4; rif[1] = d2; rif[2] = a1; rif[3] = a2;
        rif[4] = f3; rif[5] = a4; rif[6] = a5; rif[7] = f7;
    }
    __syncthreads();  // misc staged

    // ---- e1: 8 -> 32 ----
    float h1v[32];
    #pragma unroll
    for (int o4 = 0; o4 < 8; o4++) {
        float4 bb = *(const float4*)&ms[MSF_B1 + o4 * 4];
        h1v[o4 * 4 + 0] = bb.x; h1v[o4 * 4 + 1] = bb.y;
        h1v[o4 * 4 + 2] = bb.z; h1v[o4 * 4 + 3] = bb.w;
    }
    #pragma unroll
    for (int c = 0; c < 8; c++) {
        float rc = rif[c];
        #pragma unroll
        for (int o4 = 0; o4 < 8; o4++) {
            float4 w = *(const float4*)&ms[MSF_W1T + c * 32 + o4 * 4];
            h1v[o4 * 4 + 0] += w.x * rc; h1v[o4 * 4 + 1] += w.y * rc;
            h1v[o4 * 4 + 2] += w.z * rc; h1v[o4 * 4 + 3] += w.w * rc;
        }
    }
    #pragma unroll
    for (int o = 0; o < 32; o++) h1v[o] = fmaxf(h1v[o], 0.0f);

    // ---- e2: 32 -> 64 (this half's 32 channels) ----
    float acc2[32];
    {
        const int o0 = 32 * ohalf;
        #pragma unroll
        for (int j4 = 0; j4 < 8; j4++) {
            float4 bb = *(const float4*)&ms[MSF_B2 + o0 + j4 * 4];
            acc2[j4 * 4 + 0] = bb.x; acc2[j4 * 4 + 1] = bb.y;
            acc2[j4 * 4 + 2] = bb.z; acc2[j4 * 4 + 3] = bb.w;
        }
        #pragma unroll 4
        for (int c = 0; c < 32; c++) {
            float hc = h1v[c];
            #pragma unroll
            for (int j4 = 0; j4 < 8; j4++) {
                float4 w = *(const float4*)&ms[MSF_W2T + c * 64 + o0 + j4 * 4];
                acc2[j4 * 4 + 0] += w.x * hc; acc2[j4 * 4 + 1] += w.y * hc;
                acc2[j4 * 4 + 2] += w.z * hc; acc2[j4 * 4 + 3] += w.w * hc;
            }
        }
    }
    // e2 channels -> A words [row][16*ohalf + jp]
    #pragma unroll
    for (int jp = 0; jp < 16; jp++) {
        float v0 = fmaxf(acc2[2 * jp], 0.0f);
        float v1 = fmaxf(acc2[2 * jp + 1], 0.0f);
        ah[row * AST + 16 * ohalf + jp] = pack_h(v0, v1);
    }
    // prev gather -> A words [row][32 + 16*ohalf + jp]
    {
        const float* pb = prev + ((size_t)b * 64 + 32 * (size_t)ohalf) * NPTS + g;
        #pragma unroll
        for (int jp = 0; jp < 16; jp++) {
            float v0 = pb[(size_t)(2 * jp) * NPTS];
            float v1 = pb[(size_t)(2 * jp + 1) * NPTS];
            ah[row * AST + 32 + 16 * ohalf + jp] = pack_h(v0, v1);
        }
    }
    __syncthreads();

    const int mg = warp >> 2;       // 0..1 : rows 64*mg
    const int ng = warp & 3;        // 0..3
    const int jj = lane & 3;
    const int qq = lane >> 2;
    const uint32_t sbAH = sb + SM_AH;

    // ================= f1: 128 -> 128 (acc in regs; A reused after sync) =================
    float acc[4][4][4];
    {
        #pragma unroll
        for (int nt = 0; nt < 4; nt++) {
            int cb = (ng * 4 + nt) * 8 + 2 * jj;
            float be = ms[MSF_FB1 + cb], bo = ms[MSF_FB1 + cb + 1];
            #pragma unroll
            for (int mt = 0; mt < 4; mt++) {
                acc[mt][nt][0] = be; acc[mt][nt][1] = bo;
                acc[mt][nt][2] = be; acc[mt][nt][3] = bo;
            }
        }
        uint2 bcur[4];
        #pragma unroll
        for (int nt = 0; nt < 4; nt++)
            bcur[nt] = __ldg(&g_bf1[(ng * 4 + nt) * 256 + lane]);
        #pragma unroll
        for (int sstep = 0; sstep < 8; sstep++) {
            uint2 bnxt[4];
            if (sstep < 7) {
                #pragma unroll
                for (int nt = 0; nt < 4; nt++)
                    bnxt[nt] = __ldg(&g_bf1[(ng * 4 + nt) * 256 + (sstep + 1) * 32 + lane]);
            }
            #pragma unroll
            for (int mt = 0; mt < 4; mt++) {
                uint32_t a4[4];
                lda4(a4, sbAH, mg * 64 + 16 * mt, sstep, lane);
                #pragma unroll
                for (int nt = 0; nt < 4; nt++)
                    mma_f16(acc[mt][nt], a4, bcur[nt].x, bcur[nt].y);
            }
            if (sstep < 7) {
                #pragma unroll
                for (int nt = 0; nt < 4; nt++) bcur[nt] = bnxt[nt];
            }
        }
    }
    __syncthreads();   // all f1 reads of A complete — safe to overwrite

    // relu + store f1 outputs into the SAME A image
    #pragma unroll
    for (int mt = 0; mt < 4; mt++) {
        #pragma unroll
        for (int nt = 0; nt < 4; nt++) {
            int r0 = mg * 64 + 16 * mt + qq;
            int wi = (ng * 4 + nt) * 4 + jj;
            float v0 = fmaxf(acc[mt][nt][0], 0.0f), v1 = fmaxf(acc[mt][nt][1], 0.0f);
            ah[r0 * AST + wi] = pack_h(v0, v1);
            float v2 = fmaxf(acc[mt][nt][2], 0.0f), v3 = fmaxf(acc[mt][nt][3], 0.0f);
            ah[(r0 + 8) * AST + wi] = pack_h(v2, v3);
        }
    }
    __syncthreads();

    // ================= f2: 128 -> 256 (+ k-max) =================
    #pragma unroll 1
    for (int cnk = 0; cnk < 2; cnk++) {
        const int ntg0 = ng * 8 + cnk * 4;
        #pragma unroll
        for (int nt = 0; nt < 4; nt++) {
            int cb = (ntg0 + nt) * 8 + 2 * jj;
            float be = ms[MSF_FB2 + cb], bo = ms[MSF_FB2 + cb + 1];
            #pragma unroll
            for (int mt = 0; mt < 4; mt++) {
                acc[mt][nt][0] = be; acc[mt][nt][1] = bo;
                acc[mt][nt][2] = be; acc[mt][nt][3] = bo;
            }
        }
        uint2 bcur[4];
        #pragma unroll
        for (int nt = 0; nt < 4; nt++)
            bcur[nt] = __ldg(&g_bf2[(ntg0 + nt) * 256 + lane]);
        #pragma unroll
        for (int sstep = 0; sstep < 8; sstep++) {
            uint2 bnxt[4];
            if (sstep < 7) {
                #pragma unroll
                for (int nt = 0; nt < 4; nt++)
                    bnxt[nt] = __ldg(&g_bf2[(ntg0 + nt) * 256 + (sstep + 1) * 32 + lane]);
            }
            #pragma unroll
            for (int mt = 0; mt < 4; mt++) {
                uint32_t a4[4];
                lda4(a4, sbAH, mg * 64 + 16 * mt, sstep, lane);
                #pragma unroll
                for (int nt = 0; nt < 4; nt++)
                    mma_f16(acc[mt][nt], a4, bcur[nt].x, bcur[nt].y);
            }
            if (sstep < 7) {
                #pragma unroll
                for (int nt = 0; nt < 4; nt++) bcur[nt] = bnxt[nt];
            }
        }
        // relu + max over 16 rows + stage
        #pragma unroll
        for (int mt = 0; mt < 4; mt++) {
            const int sl = 2 * mg + (mt >> 1);
            const int kh = mt & 1;
            #pragma unroll
            for (int nt = 0; nt < 4; nt++) {
                float me = fmaxf(fmaxf(acc[mt][nt][0], acc[mt][nt][2]), 0.0f);
                float mo = fmaxf(fmaxf(acc[mt][nt][1], acc[mt][nt][3]), 0.0f);
                me = fmaxf(me, __shfl_xor_sync(0xffffffffu, me, 4));
                me = fmaxf(me, __shfl_xor_sync(0xffffffffu, me, 8));
                me = fmaxf(me, __shfl_xor_sync(0xffffffffu, me, 16));
                mo = fmaxf(mo, __shfl_xor_sync(0xffffffffu, mo, 4));
                mo = fmaxf(mo, __shfl_xor_sync(0xffffffffu, mo, 8));
                mo = fmaxf(mo, __shfl_xor_sync(0xffffffffu, mo, 16));
                if (lane < 4) {
                    int col = (ntg0 + nt) * 8 + 2 * lane;
                    part[sl * 512 + kh * 256 + col] = me;
                    part[sl * 512 + kh * 256 + col + 1] = mo;
                }
            }
        }
    }
    __syncthreads();

    // ---- final: combine k-halves, coalesced store ----
    {
        float4 v;
        v.x = fmaxf(part[0 * 512 + t], part[0 * 512 + 256 + t]);
        v.y = fmaxf(part[1 * 512 + t], part[1 * 512 + 256 + t]);
        v.z = fmaxf(part[2 * 512 + t], part[2 * 512 + 256 + t]);
        v.w = fmaxf(part[3 * 512 + t], part[3 * 512 + 256 + t]);
        *(float4*)(out + ((size_t)(b * 256 + t)) * SSZ + s_base) = v;
    }
}

extern "C" void kernel_launch(void* const* d_in, const int* in_sizes, int n_in,
                              void* d_out, int out_size)
{
    cudaFuncSetAttribute(main_kernel, cudaFuncAttributeMaxDynamicSharedMemorySize, SM_TOTAL);

    prep_kernel<<<64, 256>>>(
        (const float*)d_in[3],  (const float*)d_in[4],  (const float*)d_in[5],
        (const float*)d_in[6],  (const float*)d_in[7],  (const float*)d_in[8],
        (const float*)d_in[9],  (const float*)d_in[10], (const float*)d_in[11],
        (const float*)d_in[12], (const float*)d_in[13], (const float*)d_in[14],
        (const float*)d_in[15], (const float*)d_in[16], (const float*)d_in[17],
        (const float*)d_in[18], (const float*)d_in[19], (const float*)d_in[20],
        (const float*)d_in[21], (const float*)d_in[22], (const float*)d_in[23],
        (const float*)d_in[24], (const float*)d_in[25], (const float*)d_in[26]);

    main_kernel<<<2048, 256, SM_TOTAL>>>(
        (const float*)d_in[0], (const float*)d_in[1], (const float*)d_in[2], (float*)d_out);
}

// round 10
// speedup vs baseline: 3.0426x; 1.3958x over previous
#include <cuda_runtime.h>
#include <cuda_fp16.h>
#include <cstdint>
#include <math.h>

#define NPTS 8192
#define SSZ  1024
#define EPSF 1e-7f

__device__ __align__(16) float g_misc[736];
__device__ __align__(16) uint2 g_be2[512];    // e2 B-fragments (fp16)
__device__ __align__(16) uint2 g_bf1[4096];   // f1 B-fragments
__device__ __align__(16) uint2 g_bf2[8192];   // f2 B-fragments

#define MSF_W1T 0
#define MSF_B1  256
#define MSF_B2  288
#define MSF_FB1 352
#define MSF_FB2 480

// smem byte offsets
#define SM_MISC 0
#define SM_PART 3072
#define SM_A1   11264
#define SM_AH   21504
#define SM_TOTAL 56320
#define AST  68     // main A-image row stride (words)
#define A1ST 20     // h1 A-image row stride (words)

__device__ __forceinline__ uint32_t pack_h(float a, float b) {
    __half2 h = __floats2half2_rn(a, b);
    return *(uint32_t*)&h;
}
__device__ __forceinline__ uint32_t smem_u32(const void* p) {
    uint32_t a;
    asm("{ .reg .u64 t; cvta.to.shared.u64 t, %1; cvt.u32.u64 %0, t; }" : "=r"(a) : "l"(p));
    return a;
}
__device__ __forceinline__ void lda4s(uint32_t r[4], uint32_t sbase, int rowbase, int s,
                                      int lane, int stw) {
    int row = rowbase + (lane & 7) + ((lane >> 3) & 1) * 8;
    int kw  = 8 * s + ((lane >> 4) << 2);
    uint32_t addr = sbase + (uint32_t)(row * (stw * 4) + kw * 4);
    asm volatile("ldmatrix.sync.aligned.m8n8.x4.shared.b16 {%0,%1,%2,%3}, [%4];"
        : "=r"(r[0]), "=r"(r[1]), "=r"(r[2]), "=r"(r[3]) : "r"(addr));
}
__device__ __forceinline__ void mma_f16(float* d, const uint32_t* a, uint32_t b0, uint32_t b1) {
    asm volatile("mma.sync.aligned.m16n8k16.row.col.f32.f16.f16.f32 "
        "{%0,%1,%2,%3}, {%4,%5,%6,%7}, {%8,%9}, {%0,%1,%2,%3};"
        : "+f"(d[0]), "+f"(d[1]), "+f"(d[2]), "+f"(d[3])
        : "r"(a[0]), "r"(a[1]), "r"(a[2]), "r"(a[3]), "r"(b0), "r"(b1));
}
__device__ __forceinline__ float clamp1(float x) {
    return fminf(fmaxf(x, -1.0f + EPSF), 1.0f - EPSF);
}

// ---------------- prep: fold BN, pack fp16 fragments ----------------
__global__ void prep_kernel(
    const float* __restrict__ ew1, const float* __restrict__ eb1, const float* __restrict__ eg1,
    const float* __restrict__ ebeta1, const float* __restrict__ em1, const float* __restrict__ ev1,
    const float* __restrict__ ew2, const float* __restrict__ eb2, const float* __restrict__ eg2,
    const float* __restrict__ ebeta2, const float* __restrict__ em2, const float* __restrict__ ev2,
    const float* __restrict__ fw1, const float* __restrict__ fb1, const float* __restrict__ fg1,
    const float* __restrict__ fbeta1, const float* __restrict__ fm1, const float* __restrict__ fv1,
    const float* __restrict__ fw2, const float* __restrict__ fb2, const float* __restrict__ fg2,
    const float* __restrict__ fbeta2, const float* __restrict__ fm2, const float* __restrict__ fv2)
{
    int t = blockIdx.x * blockDim.x + threadIdx.x;
    int stride = gridDim.x * blockDim.x;

    // f1 B-fragments
    for (int i = t; i < 4096; i += stride) {
        int lane = i & 31, s = (i >> 5) & 7, nt = i >> 8;
        int n = nt * 8 + (lane >> 2);
        int k0 = s * 16 + (lane & 3) * 2;
        float sc = fg1[n] * rsqrtf(fv1[n] + 1e-5f);
        uint2 r;
        r.x = pack_h(fw1[n * 128 + k0] * sc,     fw1[n * 128 + k0 + 1] * sc);
        r.y = pack_h(fw1[n * 128 + k0 + 8] * sc, fw1[n * 128 + k0 + 9] * sc);
        g_bf1[i] = r;
    }
    // f2 B-fragments
    for (int i = t; i < 8192; i += stride) {
        int lane = i & 31, s = (i >> 5) & 7, nt = i >> 8;
        int n = nt * 8 + (lane >> 2);
        int k0 = s * 16 + (lane & 3) * 2;
        float sc = fg2[n] * rsqrtf(fv2[n] + 1e-5f);
        uint2 r;
        r.x = pack_h(fw2[n * 128 + k0] * sc,     fw2[n * 128 + k0 + 1] * sc);
        r.y = pack_h(fw2[n * 128 + k0 + 8] * sc, fw2[n * 128 + k0 + 9] * sc);
        g_be2[0] = g_be2[0]; // no-op to keep structure clear
        g_bf2[i] = r;
    }
    // e2 B-fragments: N=64, K=32 -> 8 n-tiles x 2 k-steps x 32 lanes
    for (int i = t; i < 512; i += stride) {
        int lane = i & 31, s = (i >> 5) & 1, nt = i >> 6;
        int n = nt * 8 + (lane >> 2);
        int k0 = s * 16 + (lane & 3) * 2;
        float sc = eg2[n] * rsqrtf(ev2[n] + 1e-5f);
        uint2 r;
        r.x = pack_h(ew2[n * 32 + k0] * sc,     ew2[n * 32 + k0 + 1] * sc);
        r.y = pack_h(ew2[n * 32 + k0 + 8] * sc, ew2[n * 32 + k0 + 9] * sc);
        g_be2[i] = r;
    }
    // e1 folded weights [c][o] + biases
    for (int i = t; i < 256; i += stride) {
        int o = i & 31, c = i >> 5;
        g_misc[MSF_W1T + c * 32 + o] = ew1[o * 8 + c] * (eg1[o] * rsqrtf(ev1[o] + 1e-5f));
    }
    for (int i = t; i < 32; i += stride) {
        float sc = eg1[i] * rsqrtf(ev1[i] + 1e-5f);
        g_misc[MSF_B1 + i] = (eb1[i] - em1[i]) * sc + ebeta1[i];
    }
    for (int i = t; i < 64; i += stride) {
        float sc = eg2[i] * rsqrtf(ev2[i] + 1e-5f);
        g_misc[MSF_B2 + i] = (eb2[i] - em2[i]) * sc + ebeta2[i];
    }
    for (int i = t; i < 128; i += stride) {
        float sc = fg1[i] * rsqrtf(fv1[i] + 1e-5f);
        g_misc[MSF_FB1 + i] = (fb1[i] - fm1[i]) * sc + fbeta1[i];
    }
    for (int i = t; i < 256; i += stride) {
        float sc = fg2[i] * rsqrtf(fv2[i] + 1e-5f);
        g_misc[MSF_FB2 + i] = (fb2[i] - fm2[i]) * sc + fbeta2[i];
    }
}

// ---------------- main kernel: 256 threads, 8 warps, 2 CTAs/SM ----------------
__global__ __launch_bounds__(256, 2) void main_kernel(
    const float* __restrict__ contour,
    const float* __restrict__ loa,
    const float* __restrict__ prev,
    float* __restrict__ out)
{
    extern __shared__ char smem[];
    const uint32_t sb = smem_u32(smem);
    float* ms = (float*)(smem + SM_MISC);
    float* part = (float*)(smem + SM_PART);
    uint32_t* a1w = (uint32_t*)(smem + SM_A1);
    uint32_t* ah = (uint32_t*)(smem + SM_AH);

    const int t = threadIdx.x;
    const int lane = t & 31;
    const int warp = t >> 5;
    const int b = blockIdx.x >> 8;
    const int s_base = (blockIdx.x & 255) * 4;

    // stage misc weights to smem (736 floats = 184 uint4)
    {
        const uint4* src = (const uint4*)g_misc;
        uint4* dst = (uint4*)ms;
        for (int i = t; i < 184; i += 256) dst[i] = src[i];
    }

    // ---- geometry (per row; two channel-halves per row) ----
    const int row = t & 127;
    const int ohalf = t >> 7;
    const int k = row & 31;
    const int s = s_base + (row >> 5);
    const int nii = (int)(((long long)s * (NPTS - 1)) / (SSZ - 1));
    const int g  = (nii - 16 + k) & (NPTS - 1);
    const int gp = (nii - 16 + k - 1) & (NPTS - 1);

    float rif[8];
    {
        const float2* cptr = (const float2*)(contour + (size_t)b * NPTS * 2);
        const float2* lptr = (const float2*)(loa + (size_t)b * NPTS * 2);
        float2 xi = cptr[g], lxi = lptr[g];
        float2 xp = cptr[gp], lxp = lptr[gp];
        float2 ci = cptr[nii], lci = lptr[nii];

        float vx = xi.x - ci.x, vy = xi.y - ci.y;
        float f4 = sqrtf(vx * vx + vy * vy);
        float inv = 1.0f / (f4 + EPSF);
        float ux = vx * inv, uy = vy * inv;
        float a1 = lci.x * ux + lci.y * uy;
        float a2 = -(lxi.x * ux + lxi.y * uy);
        float f3 = ((a1 < a2) ? 1.0f : -1.0f) * acosf(clamp1(lxi.x * lci.x + lxi.y * lci.y));

        float vpx, vpy, lmx, lmy, rux, ruy;
        if (k > 0) {
            vpx = xi.x - xp.x; vpy = xi.y - xp.y;
            lmx = lxp.x;       lmy = lxp.y;
            float pvx = xp.x - ci.x, pvy = xp.y - ci.y;
            float invp = 1.0f / (sqrtf(pvx * pvx + pvy * pvy) + EPSF);
            rux = pvx * invp; ruy = pvy * invp;
        } else {
            vpx = vpy = lmx = lmy = rux = ruy = 0.0f;
        }
        float f8 = sqrtf(vpx * vpx + vpy * vpy);
        float inv8 = 1.0f / (f8 + EPSF);
        float upx = vpx * inv8, upy = vpy * inv8;
        float a4 = upx * lxi.x + upy * lxi.y;
        float a5 = upx * lmx + upy * lmy;
        float f7 = ((a4 < a5) ? 1.0f : -1.0f) * acosf(clamp1(lxi.x * lmx + lxi.y * lmy));
        float d2 = acosf(clamp1(ux * rux + uy * ruy));

        rif[0] = f4; rif[1] = d2; rif[2] = a1; rif[3] = a2;
        rif[4] = f3; rif[5] = a4; rif[6] = a5; rif[7] = f7;
    }
    __syncthreads();  // misc staged

    // ---- e1: 8 -> 32, this half's 16 channels only ----
    {
        const int o0 = 16 * ohalf;
        float h1v[16];
        #pragma unroll
        for (int j4 = 0; j4 < 4; j4++) {
            float4 bb = *(const float4*)&ms[MSF_B1 + o0 + j4 * 4];
            h1v[j4 * 4 + 0] = bb.x; h1v[j4 * 4 + 1] = bb.y;
            h1v[j4 * 4 + 2] = bb.z; h1v[j4 * 4 + 3] = bb.w;
        }
        #pragma unroll
        for (int c = 0; c < 8; c++) {
            float rc = rif[c];
            #pragma unroll
            for (int j4 = 0; j4 < 4; j4++) {
                float4 w = *(const float4*)&ms[MSF_W1T + c * 32 + o0 + j4 * 4];
                h1v[j4 * 4 + 0] += w.x * rc; h1v[j4 * 4 + 1] += w.y * rc;
                h1v[j4 * 4 + 2] += w.z * rc; h1v[j4 * 4 + 3] += w.w * rc;
            }
        }
        uint32_t hw[8];
        #pragma unroll
        for (int jp = 0; jp < 8; jp++)
            hw[jp] = pack_h(fmaxf(h1v[2 * jp], 0.0f), fmaxf(h1v[2 * jp + 1], 0.0f));
        int wbase = row * A1ST + 8 * ohalf;
        *(uint4*)&a1w[wbase]     = make_uint4(hw[0], hw[1], hw[2], hw[3]);
        *(uint4*)&a1w[wbase + 4] = make_uint4(hw[4], hw[5], hw[6], hw[7]);
    }
    // ---- prev gather -> main A words [row][32 + 16*ohalf .. +16), vectorized ----
    {
        const float* pb = prev + ((size_t)b * 64 + 32 * (size_t)ohalf) * NPTS + g;
        uint32_t pw[16];
        #pragma unroll
        for (int jp = 0; jp < 16; jp++)
            pw[jp] = pack_h(pb[(size_t)(2 * jp) * NPTS], pb[(size_t)(2 * jp + 1) * NPTS]);
        int wbase = row * AST + 32 + 16 * ohalf;
        #pragma unroll
        for (int q = 0; q < 4; q++)
            *(uint4*)&ah[wbase + 4 * q] =
                make_uint4(pw[4 * q], pw[4 * q + 1], pw[4 * q + 2], pw[4 * q + 3]);
    }
    __syncthreads();

    const int mg = warp >> 2;       // 0..1 : rows 64*mg
    const int ng = warp & 3;        // 0..3
    const int jj = lane & 3;
    const int qq = lane >> 2;
    const uint32_t sbA1 = sb + SM_A1;
    const uint32_t sbAH = sb + SM_AH;

    float acc[4][4][4];

    // ================= e2: 32 -> 64 on HMMA (A1 -> main A cols 0..15) =================
    {
        #pragma unroll
        for (int nt = 0; nt < 2; nt++) {
            int cb = (ng * 2 + nt) * 8 + 2 * jj;
            float be = ms[MSF_B2 + cb], bo = ms[MSF_B2 + cb + 1];
            #pragma unroll
            for (int mt = 0; mt < 4; mt++) {
                acc[mt][nt][0] = be; acc[mt][nt][1] = bo;
                acc[mt][nt][2] = be; acc[mt][nt][3] = bo;
            }
        }
        uint2 b2f[2][2];
        #pragma unroll
        for (int nt = 0; nt < 2; nt++)
            #pragma unroll
            for (int ss = 0; ss < 2; ss++)
                b2f[nt][ss] = __ldg(&g_be2[(ng * 2 + nt) * 64 + ss * 32 + lane]);
        #pragma unroll
        for (int ss = 0; ss < 2; ss++) {
            #pragma unroll
            for (int mt = 0; mt < 4; mt++) {
                uint32_t a4[4];
                lda4s(a4, sbA1, mg * 64 + 16 * mt, ss, lane, A1ST);
                #pragma unroll
                for (int nt = 0; nt < 2; nt++)
                    mma_f16(acc[mt][nt], a4, b2f[nt][ss].x, b2f[nt][ss].y);
            }
        }
        // relu + pack into main A words 0..15 (conflict-free fragment STS)
        #pragma unroll
        for (int mt = 0; mt < 4; mt++) {
            #pragma unroll
            for (int nt = 0; nt < 2; nt++) {
                int r0 = mg * 64 + 16 * mt + qq;
                int wi = (ng * 2 + nt) * 4 + jj;
                ah[r0 * AST + wi] =
                    pack_h(fmaxf(acc[mt][nt][0], 0.0f), fmaxf(acc[mt][nt][1], 0.0f));
                ah[(r0 + 8) * AST + wi] =
                    pack_h(fmaxf(acc[mt][nt][2], 0.0f), fmaxf(acc[mt][nt][3], 0.0f));
            }
        }
    }
    __syncthreads();

    // ================= f1: 128 -> 128 (acc in regs; A reused after sync) =================
    {
        #pragma unroll
        for (int nt = 0; nt < 4; nt++) {
            int cb = (ng * 4 + nt) * 8 + 2 * jj;
            float be = ms[MSF_FB1 + cb], bo = ms[MSF_FB1 + cb + 1];
            #pragma unroll
            for (int mt = 0; mt < 4; mt++) {
                acc[mt][nt][0] = be; acc[mt][nt][1] = bo;
                acc[mt][nt][2] = be; acc[mt][nt][3] = bo;
            }
        }
        uint2 bcur[4];
        #pragma unroll
        for (int nt = 0; nt < 4; nt++)
            bcur[nt] = __ldg(&g_bf1[(ng * 4 + nt) * 256 + lane]);
        #pragma unroll
        for (int sstep = 0; sstep < 8; sstep++) {
            uint2 bnxt[4];
            if (sstep < 7) {
                #pragma unroll
                for (int nt = 0; nt < 4; nt++)
                    bnxt[nt] = __ldg(&g_bf1[(ng * 4 + nt) * 256 + (sstep + 1) * 32 + lane]);
            }
            #pragma unroll
            for (int mt = 0; mt < 4; mt++) {
                uint32_t a4[4];
                lda4s(a4, sbAH, mg * 64 + 16 * mt, sstep, lane, AST);
                #pragma unroll
                for (int nt = 0; nt < 4; nt++)
                    mma_f16(acc[mt][nt], a4, bcur[nt].x, bcur[nt].y);
            }
            if (sstep < 7) {
                #pragma unroll
                for (int nt = 0; nt < 4; nt++) bcur[nt] = bnxt[nt];
            }
        }
    }
    __syncthreads();   // all f1 reads of A complete — safe to overwrite

    // relu + store f1 outputs into the SAME A image
    #pragma unroll
    for (int mt = 0; mt < 4; mt++) {
        #pragma unroll
        for (int nt = 0; nt < 4; nt++) {
            int r0 = mg * 64 + 16 * mt + qq;
            int wi = (ng * 4 + nt) * 4 + jj;
            ah[r0 * AST + wi] =
                pack_h(fmaxf(acc[mt][nt][0], 0.0f), fmaxf(acc[mt][nt][1], 0.0f));
            ah[(r0 + 8) * AST + wi] =
                pack_h(fmaxf(acc[mt][nt][2], 0.0f), fmaxf(acc[mt][nt][3], 0.0f));
        }
    }
    __syncthreads();

    // ================= f2: 128 -> 256 (+ k-max) =================
    #pragma unroll 1
    for (int cnk = 0; cnk < 2; cnk++) {
        const int ntg0 = ng * 8 + cnk * 4;
        #pragma unroll
        for (int nt = 0; nt < 4; nt++) {
            int cb = (ntg0 + nt) * 8 + 2 * jj;
            float be = ms[MSF_FB2 + cb], bo = ms[MSF_FB2 + cb + 1];
            #pragma unroll
            for (int mt = 0; mt < 4; mt++) {
                acc[mt][nt][0] = be; acc[mt][nt][1] = bo;
                acc[mt][nt][2] = be; acc[mt][nt][3] = bo;
            }
        }
        uint2 bcur[4];
        #pragma unroll
        for (int nt = 0; nt < 4; nt++)
            bcur[nt] = __ldg(&g_bf2[(ntg0 + nt) * 256 + lane]);
        #pragma unroll
        for (int sstep = 0; sstep < 8; sstep++) {
            uint2 bnxt[4];
            if (sstep < 7) {
                #pragma unroll
                for (int nt = 0; nt < 4; nt++)
                    bnxt[nt] = __ldg(&g_bf2[(ntg0 + nt) * 256 + (sstep + 1) * 32 + lane]);
            }
            #pragma unroll
            for (int mt = 0; mt < 4; mt++) {
                uint32_t a4[4];
                lda4s(a4, sbAH, mg * 64 + 16 * mt, sstep, lane, AST);
                #pragma unroll
                for (int nt = 0; nt < 4; nt++)
                    mma_f16(acc[mt][nt], a4, bcur[nt].x, bcur[nt].y);
            }
            if (sstep < 7) {
                #pragma unroll
                for (int nt = 0; nt < 4; nt++) bcur[nt] = bnxt[nt];
            }
        }
        // relu + max over 16 rows + stage
        #pragma unroll
        for (int mt = 0; mt < 4; mt++) {
            const int sl = 2 * mg + (mt >> 1);
            const int kh = mt & 1;
            #pragma unroll
            for (int nt = 0; nt < 4; nt++) {
                float me = fmaxf(fmaxf(acc[mt][nt][0], acc[mt][nt][2]), 0.0f);
                float mo = fmaxf(fmaxf(acc[mt][nt][1], acc[mt][nt][3]), 0.0f);
                me = fmaxf(me, __shfl_xor_sync(0xffffffffu, me, 4));
                me = fmaxf(me, __shfl_xor_sync(0xffffffffu, me, 8));
                me = fmaxf(me, __shfl_xor_sync(0xffffffffu, me, 16));
                mo = fmaxf(mo, __shfl_xor_sync(0xffffffffu, mo, 4));
                mo = fmaxf(mo, __shfl_xor_sync(0xffffffffu, mo, 8));
                mo = fmaxf(mo, __shfl_xor_sync(0xffffffffu, mo, 16));
                if (lane < 4) {
                    int col = (ntg0 + nt) * 8 + 2 * lane;
                    part[sl * 512 + kh * 256 + col] = me;
                    part[sl * 512 + kh * 256 + col + 1] = mo;
                }
            }
        }
    }
    __syncthreads();

    // ---- final: combine k-halves, coalesced store ----
    {
        float4 v;
        v.x = fmaxf(part[0 * 512 + t], part[0 * 512 + 256 + t]);
        v.y = fmaxf(part[1 * 512 + t], part[1 * 512 + 256 + t]);
        v.z = fmaxf(part[2 * 512 + t], part[2 * 512 + 256 + t]);
        v.w = fmaxf(part[3 * 512 + t], part[3 * 512 + 256 + t]);
        *(float4*)(out + ((size_t)(b * 256 + t)) * SSZ + s_base) = v;
    }
}

extern "C" void kernel_launch(void* const* d_in, const int* in_sizes, int n_in,
                              void* d_out, int out_size)
{
    cudaFuncSetAttribute(main_kernel, cudaFuncAttributeMaxDynamicSharedMemorySize, SM_TOTAL);

    prep_kernel<<<64, 256>>>(
        (const float*)d_in[3],  (const float*)d_in[4],  (const float*)d_in[5],
        (const float*)d_in[6],  (const float*)d_in[7],  (const float*)d_in[8],
        (const float*)d_in[9],  (const float*)d_in[10], (const float*)d_in[11],
        (const float*)d_in[12], (const float*)d_in[13], (const float*)d_in[14],
        (const float*)d_in[15], (const float*)d_in[16], (const float*)d_in[17],
        (const float*)d_in[18], (const float*)d_in[19], (const float*)d_in[20],
        (const float*)d_in[21], (const float*)d_in[22], (const float*)d_in[23],
        (const float*)d_in[24], (const float*)d_in[25], (const float*)d_in[26]);

    main_kernel<<<2048, 256, SM_TOTAL>>>(
        (const float*)d_in[0], (const float*)d_in[1], (const float*)d_in[2], (float*)d_out);
}